// round 5
// baseline (speedup 1.0000x reference)
#include <cuda_runtime.h>
#include <math.h>

// Problem constants
#define NB 16     // batch
#define NO 64     // objects
#define NK 63     // O-1
#define NC 8      // C
#define SEG 128   // per-segment width
#define NI 640    // num_in
#define NAC 24    // A*C
#define WPAD 33   // float4 row stride in smem (132 words)
#define THRv 0.2f
#define TTHR 0.19737532f   // tanh(0.2)
#define TPB 8     // GEMM tiles per block

// Scratch (device globals: no allocation allowed)
__device__ float g_DB [NB * NO * NK * 24];  // binary dots, cols 0:24, tile-major [tile][k][24]
__device__ float g_DBT[NB * NK * NO * 24];  // binary dots, cols 24:48, transposed [b][row][j][24]
__device__ float g_DU [NB * NO * 48];       // unary dots: [0:24]=w_u0, [24:48]=w_u1
__device__ float g_DN [NB * NAC];           // nullary dots
__device__ float g_andbias[NAC];
__device__ float g_orbias[3];
__device__ float g_nullpart[NB * NO * NC];
__device__ int   g_cnt[NB];                 // zero-init; self-resetting

__device__ __forceinline__ float tanhapx(float x) {
    float y; asm("tanh.approx.f32 %0, %1;" : "=f"(y) : "f"(x)); return y;
}
__device__ __forceinline__ void ffma2(unsigned long long& d,
                                      unsigned long long a, unsigned long long b) {
    asm("fma.rn.f32x2 %0, %1, %2, %0;" : "+l"(d) : "l"(a), "l"(b));
}
__device__ __forceinline__ float f2sum(unsigned long long v) {
    float lo, hi; asm("mov.b64 {%0, %1}, %2;" : "=f"(lo), "=f"(hi) : "l"(v));
    return lo + hi;
}
__device__ __forceinline__ void cpasync16(void* sdst, const void* gsrc) {
    unsigned s = (unsigned)__cvta_generic_to_shared(sdst);
    asm volatile("cp.async.cg.shared.global [%0], [%1], 16;" :: "r"(s), "l"(gsrc));
}

// ---------------------------------------------------------------------------
// GEMM: 128 threads/block. Blocks 0..127: binary (8 tiles each).
// Blocks 128..129: unary (8 tiles each). Block 130: biases. Block 131: DN.
// Per block: weights loaded once; row tiles double-buffered via cp.async.
__global__ __launch_bounds__(128) void gemm_kernel(
    const float* __restrict__ binary,
    const float* __restrict__ unary,
    const float* __restrict__ nullary,
    const float* __restrict__ andk,
    const float* __restrict__ ork)
{
    extern __shared__ float4 sm[];
    int blk = blockIdx.x;
    int tid = threadIdx.x;

    if (blk >= 130) {
        if (blk == 130) {
            __shared__ float sred[NAC][4];
            if (tid < 96) {
                int row = tid >> 2, part = tid & 3;
                const float* w = andk + (size_t)row * NI + part * 160;
                float s = 0.f;
                #pragma unroll 8
                for (int k = 0; k < 160; k++) { float v = w[k]; s += v * v; }
                sred[row][part] = s;
            }
            __syncthreads();
            if (tid < NAC) {
                float s = sred[tid][0] + sred[tid][1] + sred[tid][2] + sred[tid][3];
                g_andbias[tid] = THRv - s * TTHR;
            } else if (tid < 27) {
                int a = tid - NAC;
                float s = 0.f;
                #pragma unroll
                for (int c = 0; c < NC; c++) { float v = ork[a * NC + c]; s += v * v; }
                g_orbias[a] = s * TTHR - THRv;
            }
        } else {
            for (int d = tid; d < NB * NAC; d += 128) {
                int b = d / NAC, ac = d % NAC;
                const float* w = andk + (size_t)ac * NI;
                const float* nv = nullary + b * SEG;
                float s = 0.f;
                #pragma unroll 8
                for (int k = 0; k < SEG; k++) s += nv[k] * w[k];
                g_DN[d] = s;
            }
        }
        return;
    }

    bool isU = blk >= 128;
    float4* ws  = sm;                      // 48 x WPAD
    float4* rsb[2] = { sm + 48 * WPAD, sm + 48 * WPAD + 64 * WPAD };
    int nrows = isU ? 64 : NK;
    int t0 = blk * TPB;                    // first tile id (1024 boundary aligns: 128*8)

    // Load weight tile once
    const float4* andk4 = (const float4*)andk;     // and_kernel row = 160 float4
    int wbase = isU ? 32 : 96;
    for (int idx = tid; idx < 48 * 32; idx += 128) {
        int wr = idx >> 5, t = idx & 31;
        int ac = wr % NAC, seg = wr / NAC;
        ws[wr * WPAD + t] = __ldg(andk4 + ac * 160 + wbase + seg * 32 + t);
    }
    // Zero pad row 63 in both buffers (binary only; cp.async never writes it)
    if (!isU && tid < 32) {
        rsb[0][63 * WPAD + tid] = make_float4(0.f, 0.f, 0.f, 0.f);
        rsb[1][63 * WPAD + tid] = make_float4(0.f, 0.f, 0.f, 0.f);
    }

    // Issue helper (macro-style via lambda)
    auto issue = [&](int tt, int bufi) {
        const float4* src = isU
            ? ((const float4*)unary  + (size_t)(t0 + tt - 1024) * 2048)
            : ((const float4*)binary + (size_t)(t0 + tt) * (NK * 32));
        float4* dst = rsb[bufi];
        for (int idx = tid; idx < nrows * 32; idx += 128)
            cpasync16(&dst[(idx >> 5) * WPAD + (idx & 31)], src + idx);
        asm volatile("cp.async.commit_group;");
    };

    issue(0, 0);

    int rg = tid >> 4;   // 8 row groups x 8 rows
    int cg = tid & 15;   // 16 col groups x 3 cols

    for (int tt = 0; tt < TPB; tt++) {
        if (tt + 1 < TPB) {
            issue(tt + 1, (tt + 1) & 1);
            asm volatile("cp.async.wait_group 1;");
        } else {
            asm volatile("cp.async.wait_group 0;");
        }
        __syncthreads();

        const float4* rs = rsb[tt & 1];
        unsigned long long acc[8][3];
        #pragma unroll
        for (int r = 0; r < 8; r++)
            #pragma unroll
            for (int c = 0; c < 3; c++) acc[r][c] = 0ULL;

        const ulonglong2* rp  = (const ulonglong2*)(rs + (rg * 8) * WPAD);
        const ulonglong2* wp0 = (const ulonglong2*)(ws + (cg * 3) * WPAD);
        const ulonglong2* wp1 = wp0 + WPAD;
        const ulonglong2* wp2 = wp1 + WPAD;
        #pragma unroll 2
        for (int k = 0; k < 32; k++) {
            ulonglong2 w0 = wp0[k], w1 = wp1[k], w2 = wp2[k];
            #pragma unroll
            for (int rr = 0; rr < 8; rr++) {
                ulonglong2 rv = rp[rr * WPAD + k];
                ffma2(acc[rr][0], rv.x, w0.x); ffma2(acc[rr][0], rv.y, w0.y);
                ffma2(acc[rr][1], rv.x, w1.x); ffma2(acc[rr][1], rv.y, w1.y);
                ffma2(acc[rr][2], rv.x, w2.x); ffma2(acc[rr][2], rv.y, w2.y);
            }
        }

        int tile = t0 + tt;
        if (isU) {
            float* out = g_DU + (size_t)(tile - 1024) * NO * 48;
            #pragma unroll
            for (int rr = 0; rr < 8; rr++) {
                int r = rg * 8 + rr;
                #pragma unroll
                for (int cc = 0; cc < 3; cc++)
                    out[r * 48 + cg * 3 + cc] = f2sum(acc[rr][cc]);
            }
        } else {
            int b = tile >> 6, j = tile & 63;
            #pragma unroll
            for (int rr = 0; rr < 8; rr++) {
                int r = rg * 8 + rr;
                if (r < NK) {
                    if (cg < 8) {  // cols 0..23 -> g_DB tile-major
                        float* o = g_DB + ((size_t)tile * NK + r) * 24 + cg * 3;
                        #pragma unroll
                        for (int cc = 0; cc < 3; cc++) o[cc] = f2sum(acc[rr][cc]);
                    } else {       // cols 24..47 -> g_DBT[b][r][j]
                        float* o = g_DBT + (((size_t)b * NK + r) * NO + j) * 24 + (cg - 8) * 3;
                        #pragma unroll
                        for (int cc = 0; cc < 3; cc++) o[cc] = f2sum(acc[rr][cc]);
                    }
                }
            }
        }
        __syncthreads();
    }
}

// ---------------------------------------------------------------------------
// Combine: block = 2 tiles (same b) x 64 threads. All gmem loads coalesced
// into smem; compute from smem. Fused final-null reduce via atomic counter.
__global__ __launch_bounds__(128) void combine_kernel(
    const float* __restrict__ ork, float* __restrict__ out)
{
    __shared__ float du1s[64][25];
    __shared__ float A [2][64][25];   // db0 staging; later reused for tanh reduce
    __shared__ float Bt[2][64][25];   // db1 staging (transposed gather)
    __shared__ float base[2][NAC];
    __shared__ float colmax[2][16];
    __shared__ int isLast;

    int blk = blockIdx.x;             // 0..511
    int tx  = threadIdx.x;
    int tile = tx >> 6, k = tx & 63;
    int gi0 = blk * 2;
    int b = gi0 >> 6;

    // du1: DU[b][j][24:48] for all j (shared by both tiles)
    for (int idx = tx; idx < 64 * 24; idx += 128)
        du1s[idx / 24][idx % 24] = g_DU[(size_t)(b * NO + idx / 24) * 48 + 24 + idx % 24];

    #pragma unroll
    for (int tt = 0; tt < 2; tt++) {
        int gi = gi0 + tt, i = gi & 63;
        const float* Ab = g_DB + (size_t)gi * NK * 24;
        for (int idx = tx; idx < NK * 24; idx += 128)
            A[tt][idx / 24][idx % 24] = Ab[idx];
        const float* Tb = g_DBT + (size_t)b * NK * NO * 24;
        for (int idx = tx; idx < NK * 24; idx += 128) {
            int kk = idx / 24, c = idx % 24;
            Bt[tt][kk][c] = (kk < i) ? Tb[(((i - 1) * NO) + kk) * 24 + c]
                                     : Tb[((i * NO) + kk + 1) * 24 + c];
        }
    }
    if (tx < 48) {
        int tt = tx / 24, c = tx % 24;
        int i2 = (gi0 + tt) & 63;
        base[tt][c] = g_andbias[c] + g_DN[b * NAC + c]
                    + g_DU[(size_t)(b * NO + i2) * 48 + c];
    }
    __syncthreads();

    int gi = gi0 + tile, i = gi & 63;
    if (k < NK) {
        int j = k + (k >= i ? 1 : 0);
        float s2 = g_orbias[2];
        float tv[16];
        #pragma unroll
        for (int c = 0; c < 24; c++) {
            float s = base[tile][c] + du1s[j][c] + A[tile][k][c] + Bt[tile][k][c];
            if (c < 16) tv[c] = tanhapx(s);
            else        s2 += tanhapx(s) * __ldg(ork + 16 + (c - 16));
        }
        #pragma unroll
        for (int c = 0; c < 16; c++) A[tile][k][c] = tv[c];   // own row: race-free
        out[16 + NB * NO + (size_t)gi * NK + k] = s2;
    } else {
        #pragma unroll
        for (int c = 0; c < 16; c++) A[tile][63][c] = -2.0f;
    }
    __syncthreads();

    if (k < 16) {
        float m = A[tile][0][k];
        #pragma unroll 8
        for (int r = 1; r < 64; r++) m = fmaxf(m, A[tile][r][k]);
        colmax[tile][k] = m;
    }
    __syncthreads();
    if (k == 0) {
        float s1 = g_orbias[1];
        #pragma unroll
        for (int c = 0; c < NC; c++) s1 += colmax[tile][8 + c] * __ldg(ork + 8 + c);
        out[16 + gi] = s1;
    }
    if (k < NC) g_nullpart[gi * NC + k] = colmax[tile][k];

    // Fused final-null reduce: last of the 32 blocks for this b.
    __syncthreads();
    if (tx == 0) {
        __threadfence();
        int v = atomicAdd(&g_cnt[b], 1);
        isLast = (v == 31) ? 1 : 0;
    }
    __syncthreads();
    if (isLast) {
        __threadfence();
        if (tx < NC) {
            float m = -2.0f;
            #pragma unroll 8
            for (int r = 0; r < NO; r++)
                m = fmaxf(m, g_nullpart[(b * NO + r) * NC + tx]);
            colmax[0][tx] = m;
        }
        __syncthreads();
        if (tx == 0) {
            float s0 = g_orbias[0];
            #pragma unroll
            for (int c = 0; c < NC; c++) s0 += colmax[0][c] * __ldg(ork + c);
            out[b] = s0;
            g_cnt[b] = 0;   // reset for next graph replay
        }
    }
}

// ---------------------------------------------------------------------------
extern "C" void kernel_launch(void* const* d_in, const int* in_sizes, int n_in,
                              void* d_out, int out_size)
{
    const float* nullary = (const float*)d_in[0];
    const float* unary   = (const float*)d_in[1];
    const float* binary  = (const float*)d_in[2];
    const float* andk    = (const float*)d_in[3];
    const float* ork     = (const float*)d_in[4];
    float* out = (float*)d_out;

    size_t smK = (size_t)(48 + 2 * 64) * WPAD * sizeof(float4);  // ~90.8 KB
    cudaFuncSetAttribute(gemm_kernel, cudaFuncAttributeMaxDynamicSharedMemorySize, (int)smK);

    gemm_kernel<<<132, 128, smK>>>(binary, unary, nullary, andk, ork);
    combine_kernel<<<NB * NO / 2, 128>>>(ork, out);
}

// round 8
// speedup vs baseline: 1.0283x; 1.0283x over previous
#include <cuda_runtime.h>
#include <cuda_bf16.h>
#include <math.h>

// Problem constants
#define NB 16     // batch
#define NO 64     // objects
#define NK 63     // O-1
#define NC 8      // C
#define SEG 128   // per-segment width
#define NI 640    // num_in
#define NAC 24    // A*C
#define THRv 0.2f
#define TTHR 0.19737532f   // tanh(0.2)

// smem layout (bytes). Rows padded to 136 bf16 = 272B (odd 16B stride: ldmatrix conflict-free)
#define RPITCH 136
#define S_AHI 0
#define S_ALO 34816
#define S_WHI 69632
#define S_WLO 82688
#define S_TOTAL 95744

// Scratch (device globals). Column-major layouts for coalesced combine gathers.
__device__ float g_DB [NB * NO * NAC * 64];      // [tile][c][k]   (w_b0 dots)
__device__ float g_DBT[NB * NK * NAC * 64];      // [b][row][c][j] (w_b1 dots, transposed)
__device__ float g_DU0[NB * NO * NAC];           // [b][o][c]      (w_u0 dots)
__device__ float g_DUT[NB * NAC * 64];           // [b][c][j]      (w_u1 dots, transposed)
__device__ float g_DN [NB * NAC];
__device__ float g_andbias[NAC];
__device__ float g_orbias[3];
__device__ float g_nullpart[NB * NO * NC];
__device__ int   g_cnt[NB];                      // zero-init; self-resetting

__device__ __forceinline__ float tanhapx(float x) {
    float y; asm("tanh.approx.f32 %0, %1;" : "=f"(y) : "f"(x)); return y;
}
__device__ __forceinline__ unsigned pack_bf16x2(float a, float b) {
    __nv_bfloat162 h = __floats2bfloat162_rn(a, b);
    return *reinterpret_cast<unsigned*>(&h);
}
__device__ __forceinline__ void ldsm_x4(unsigned& r0, unsigned& r1, unsigned& r2, unsigned& r3,
                                        unsigned saddr) {
    asm volatile("ldmatrix.sync.aligned.m8n8.x4.shared.b16 {%0,%1,%2,%3}, [%4];"
                 : "=r"(r0), "=r"(r1), "=r"(r2), "=r"(r3) : "r"(saddr));
}
__device__ __forceinline__ void mma16816(float* d, const unsigned* a, const unsigned* b) {
    asm volatile(
        "mma.sync.aligned.m16n8k16.row.col.f32.bf16.bf16.f32 "
        "{%0,%1,%2,%3}, {%4,%5,%6,%7}, {%8,%9}, {%0,%1,%2,%3};"
        : "+f"(d[0]), "+f"(d[1]), "+f"(d[2]), "+f"(d[3])
        : "r"(a[0]), "r"(a[1]), "r"(a[2]), "r"(a[3]), "r"(b[0]), "r"(b[1]));
}

// ---------------------------------------------------------------------------
// GEMM via mma.sync (bf16, 3-pass split precision). 128 threads/block.
//  blocks [0,512):   binary tile pairs (tiles 2*blk, 2*blk+1): M=128 (2x63+pad)
//  blocks [512,520): unary: b = (blk-512)*2 + t
//  block 520: biases; block 521: DN
__global__ __launch_bounds__(128) void gemm_kernel(
    const float* __restrict__ binary,
    const float* __restrict__ unary,
    const float* __restrict__ nullary,
    const float* __restrict__ andk,
    const float* __restrict__ ork)
{
    extern __shared__ char smx[];
    int blk = blockIdx.x;
    int tid = threadIdx.x;

    if (blk >= 520) {
        if (blk == 520) {
            __shared__ float sred[NAC][4];
            if (tid < 96) {
                int row = tid >> 2, part = tid & 3;
                const float* w = andk + (size_t)row * NI + part * 160;
                float s = 0.f;
                #pragma unroll 8
                for (int k = 0; k < 160; k++) { float v = w[k]; s += v * v; }
                sred[row][part] = s;
            }
            __syncthreads();
            if (tid < NAC) {
                float s = sred[tid][0] + sred[tid][1] + sred[tid][2] + sred[tid][3];
                g_andbias[tid] = THRv - s * TTHR;
            } else if (tid < 27) {
                int a = tid - NAC;
                float s = 0.f;
                #pragma unroll
                for (int c = 0; c < NC; c++) { float v = ork[a * NC + c]; s += v * v; }
                g_orbias[a] = s * TTHR - THRv;
            }
        } else {
            for (int d = tid; d < NB * NAC; d += 128) {
                int b = d / NAC, ac = d % NAC;
                const float* w = andk + (size_t)ac * NI;
                const float* nv = nullary + b * SEG;
                float s = 0.f;
                #pragma unroll 8
                for (int k = 0; k < SEG; k++) s += nv[k] * w[k];
                g_DN[d] = s;
            }
        }
        return;
    }

    bool isU = blk >= 512;

    // --- Stage W (48 rows x 128) as bf16 hi/lo ---
    {
        int o1 = isU ? 128 : 384;   // w_u0 / w_b0 float offset in and_kernel row
        int o2 = isU ? 256 : 512;   // w_u1 / w_b1
        for (int idx = tid; idx < 48 * 32; idx += 128) {
            int r = idx >> 5, c4 = (idx & 31) * 4;
            int ac  = (r < 24) ? r : r - 24;
            int seg = (r < 24) ? o1 : o2;
            float4 v = *(const float4*)(andk + (size_t)ac * NI + seg + c4);
            float hx = __bfloat162float(__float2bfloat16_rn(v.x));
            float hy = __bfloat162float(__float2bfloat16_rn(v.y));
            float hz = __bfloat162float(__float2bfloat16_rn(v.z));
            float hw = __bfloat162float(__float2bfloat16_rn(v.w));
            unsigned off = (unsigned)(r * RPITCH + c4) * 2;
            *(uint2*)(smx + S_WHI + off) = make_uint2(pack_bf16x2(v.x, v.y), pack_bf16x2(v.z, v.w));
            *(uint2*)(smx + S_WLO + off) = make_uint2(pack_bf16x2(v.x - hx, v.y - hy),
                                                     pack_bf16x2(v.z - hz, v.w - hw));
        }
    }
    // --- Stage A (128 rows x 128) as bf16 hi/lo ---
    {
        for (int idx = tid; idx < 128 * 32; idx += 128) {
            int r = idx >> 5, c4 = (idx & 31) * 4;
            float4 v = make_float4(0.f, 0.f, 0.f, 0.f);
            if (isU) {
                int b = (blk - 512) * 2 + (r >> 6);
                v = *(const float4*)(unary + ((size_t)b * NO + (r & 63)) * SEG + c4);
            } else {
                int t = r >> 6, k = r & 63;
                if (k < NK) {
                    int gt = blk * 2 + t;
                    v = *(const float4*)(binary + ((size_t)gt * NK + k) * SEG + c4);
                }
            }
            float hx = __bfloat162float(__float2bfloat16_rn(v.x));
            float hy = __bfloat162float(__float2bfloat16_rn(v.y));
            float hz = __bfloat162float(__float2bfloat16_rn(v.z));
            float hw = __bfloat162float(__float2bfloat16_rn(v.w));
            unsigned off = (unsigned)(r * RPITCH + c4) * 2;
            *(uint2*)(smx + S_AHI + off) = make_uint2(pack_bf16x2(v.x, v.y), pack_bf16x2(v.z, v.w));
            *(uint2*)(smx + S_ALO + off) = make_uint2(pack_bf16x2(v.x - hx, v.y - hy),
                                                     pack_bf16x2(v.z - hz, v.w - hw));
        }
    }
    __syncthreads();

    // --- Warp-level mma: warp w owns rows [32w, 32w+32), all 48 cols ---
    int wid = tid >> 5, lane = tid & 31;
    int warpM = wid * 32;
    float acc[2][6][4];
    #pragma unroll
    for (int m = 0; m < 2; m++)
        #pragma unroll
        for (int n = 0; n < 6; n++)
            #pragma unroll
            for (int q = 0; q < 4; q++) acc[m][n][q] = 0.f;

    // ldmatrix lane address components
    int aRow = (lane & 15), aColH = (lane >> 4);          // A: row, +8-col half
    int bRow = (lane & 7) + ((lane >> 4) << 3);           // B: row within 16-row pair
    int bColH = (lane >> 3) & 1;

    const int PA[3] = { S_AHI, S_ALO, S_AHI };
    const int PW[3] = { S_WHI, S_WHI, S_WLO };
    #pragma unroll
    for (int p = 0; p < 3; p++) {
        unsigned abase = (unsigned)__cvta_generic_to_shared(smx + PA[p]);
        unsigned wbase = (unsigned)__cvta_generic_to_shared(smx + PW[p]);
        #pragma unroll
        for (int k0 = 0; k0 < 8; k0++) {
            unsigned a[2][4], b[3][4];
            #pragma unroll
            for (int mt = 0; mt < 2; mt++) {
                unsigned ad = abase + ((warpM + mt * 16 + aRow) * RPITCH
                                       + k0 * 16 + aColH * 8) * 2;
                ldsm_x4(a[mt][0], a[mt][1], a[mt][2], a[mt][3], ad);
            }
            #pragma unroll
            for (int q = 0; q < 3; q++) {
                unsigned bd = wbase + ((q * 16 + bRow) * RPITCH
                                       + k0 * 16 + bColH * 8) * 2;
                ldsm_x4(b[q][0], b[q][1], b[q][2], b[q][3], bd);
            }
            #pragma unroll
            for (int mt = 0; mt < 2; mt++)
                #pragma unroll
                for (int q = 0; q < 3; q++) {
                    mma16816(acc[mt][2 * q],     a[mt], &b[q][0]);
                    mma16816(acc[mt][2 * q + 1], a[mt], &b[q][2]);
                }
        }
    }
    __syncthreads();   // A/W dead; reuse smem for D staging

    // --- Stage D[128][48] (pitch 49 floats) ---
    float* Dst = (float*)smx;
    #pragma unroll
    for (int mt = 0; mt < 2; mt++)
        #pragma unroll
        for (int nt = 0; nt < 6; nt++) {
            int rr = warpM + mt * 16 + (lane >> 2);
            int cc = nt * 8 + (lane & 3) * 2;
            Dst[rr * 49 + cc]           = acc[mt][nt][0];
            Dst[rr * 49 + cc + 1]       = acc[mt][nt][1];
            Dst[(rr + 8) * 49 + cc]     = acc[mt][nt][2];
            Dst[(rr + 8) * 49 + cc + 1] = acc[mt][nt][3];
        }
    __syncthreads();

    // --- Coalesced global writes ---
    int t = tid >> 6, m = tid & 63;
    if (isU) {
        int b0 = (blk - 512) * 2 + t;
        #pragma unroll
        for (int c = 0; c < NAC; c++) {
            g_DU0[((size_t)b0 * NO + m) * NAC + c] = Dst[(t * 64 + m) * 49 + c];
            g_DUT[((size_t)b0 * NAC + c) * 64 + m] = Dst[(t * 64 + m) * 49 + 24 + c];
        }
    } else if (m < NK) {
        int gi = blk * 2 + t;
        int b = gi >> 6, j = gi & 63;
        #pragma unroll
        for (int c = 0; c < NAC; c++) {
            g_DB[((size_t)gi * NAC + c) * 64 + m] = Dst[(t * 64 + m) * 49 + c];
            g_DBT[(((size_t)b * NK + m) * NAC + c) * 64 + j] = Dst[(t * 64 + m) * 49 + 24 + c];
        }
    }
}

// ---------------------------------------------------------------------------
// Combine: grid 512, 256 threads = 2 tiles x (2 halves x 64 k). Coalesced
// column-major gathers. Fused final-null reduce via atomic counter.
__global__ __launch_bounds__(256) void combine_kernel(
    const float* __restrict__ ork, float* __restrict__ out)
{
    __shared__ float base[2][NAC];
    __shared__ float red[2][64][17];
    __shared__ float colmax[2][16];
    __shared__ int isLast;

    int blk  = blockIdx.x;          // 0..511
    int tile = threadIdx.x >> 7;    // 0..1
    int tid  = threadIdx.x & 127;
    int k    = tid & 63;
    int half = tid >> 6;
    int gi = blk * 2 + tile;
    int b = gi >> 6, i = gi & 63;

    if (tid < 48) {
        int tt = tid / NAC, c = tid % NAC;
        int i2 = (blk * 2 + tt) & 63;
        base[tt][c] = g_andbias[c] + g_DN[b * NAC + c] + g_DU0[((size_t)b * NO + i2) * NAC + c];
    }
    __syncthreads();

    bool act = (k < NK);
    int j  = k + (k >= i ? 1 : 0);
    int ip = (k < i) ? (i - 1) : i;
    float s2 = g_orbias[2];

    if (half == 0) {
        #pragma unroll
        for (int c = 0; c < 12; c++) {
            float v = -2.0f;
            if (act) {
                float s = base[tile][c]
                        + __ldg(&g_DUT[((size_t)b * NAC + c) * 64 + j])
                        + __ldg(&g_DB [((size_t)gi * NAC + c) * 64 + k])
                        + __ldg(&g_DBT[(((size_t)b * NK + ip) * NAC + c) * 64 + j]);
                v = tanhapx(s);
            }
            red[tile][k][c] = v;
        }
    } else {
        #pragma unroll
        for (int c = 12; c < NAC; c++) {
            float s = 0.f;
            if (act) {
                s = base[tile][c]
                  + __ldg(&g_DUT[((size_t)b * NAC + c) * 64 + j])
                  + __ldg(&g_DB [((size_t)gi * NAC + c) * 64 + k])
                  + __ldg(&g_DBT[(((size_t)b * NK + ip) * NAC + c) * 64 + j]);
            }
            if (c < 16) red[tile][k][c] = act ? tanhapx(s) : -2.0f;
            else        s2 += tanhapx(s) * __ldg(ork + 16 + (c - 16));
        }
        if (act) out[16 + NB * NO + (size_t)gi * NK + k] = s2;
    }
    __syncthreads();

    if (tid < 16) {
        float m = red[tile][0][tid];
        #pragma unroll 8
        for (int r = 1; r < 64; r++) m = fmaxf(m, red[tile][r][tid]);
        colmax[tile][tid] = m;
    }
    __syncthreads();
    if (tid == 0) {
        float s1 = g_orbias[1];
        #pragma unroll
        for (int c = 0; c < NC; c++) s1 += colmax[tile][8 + c] * __ldg(ork + 8 + c);
        out[16 + gi] = s1;
    }
    if (tid < NC) g_nullpart[gi * NC + tid] = colmax[tile][tid];

    // Fused final-null reduce: last of the 32 blocks for this b.
    __syncthreads();
    if (threadIdx.x == 0) {
        __threadfence();
        int v = atomicAdd(&g_cnt[b], 1);
        isLast = (v == 31) ? 1 : 0;
    }
    __syncthreads();
    if (isLast) {
        __threadfence();
        if (threadIdx.x < NC) {
            int c = threadIdx.x;
            float m = -2.0f;
            #pragma unroll 8
            for (int r = 0; r < NO; r++)
                m = fmaxf(m, g_nullpart[(b * NO + r) * NC + c]);
            colmax[0][c] = m;
        }
        __syncthreads();
        if (threadIdx.x == 0) {
            float s0 = g_orbias[0];
            #pragma unroll
            for (int c = 0; c < NC; c++) s0 += colmax[0][c] * __ldg(ork + c);
            out[b] = s0;
            g_cnt[b] = 0;   // reset for next graph replay
        }
    }
}

// ---------------------------------------------------------------------------
extern "C" void kernel_launch(void* const* d_in, const int* in_sizes, int n_in,
                              void* d_out, int out_size)
{
    const float* nullary = (const float*)d_in[0];
    const float* unary   = (const float*)d_in[1];
    const float* binary  = (const float*)d_in[2];
    const float* andk    = (const float*)d_in[3];
    const float* ork     = (const float*)d_in[4];
    float* out = (float*)d_out;

    cudaFuncSetAttribute(gemm_kernel, cudaFuncAttributeMaxDynamicSharedMemorySize, S_TOTAL);

    gemm_kernel<<<522, 128, S_TOTAL>>>(binary, unary, nullary, andk, ork);
    combine_kernel<<<512, 256>>>(ork, out);
}

// round 9
// speedup vs baseline: 1.1548x; 1.1230x over previous
#include <cuda_runtime.h>
#include <cuda_bf16.h>
#include <math.h>

// Problem constants
#define NB 16
#define NO 64
#define NK 63
#define NC 8
#define SEG 128
#define NI 640
#define NAC 24
#define THRv 0.2f
#define TTHR 0.19737532f   // tanh(0.2)

#define NBLK 296           // 2 per SM on 148-SM B300 (GB300 has 152: even safer)
#define NTHR 512
#define NGU 522            // units: [0,512) binary pairs, [512,520) unary, 520 bias, 521 DN

// smem layout (bytes), dynamic. bf16 rows padded to 136 elems (272B, ldmatrix conflict-free)
#define RPITCH 136
#define S_AHI 0
#define S_ALO 34816
#define S_WHI 69632
#define S_WLO 82688
#define S_TOTAL 95744
#define DPITCH 52          // D staging pitch (floats)

// Scratch (device globals; no allocation allowed)
__device__ float g_D[1040 * 64 * 48];   // [tile][row][c]; tiles 1024+b = unary
__device__ float g_DN[NB * NAC];
__device__ float g_andbias[NAC];
__device__ float g_orbias[3];
__device__ float g_nullpart[NB * NO * NC];
__device__ int   g_cnt[NB];             // zero-init; self-resetting
__device__ unsigned g_barcnt;           // zero-init; self-resetting
__device__ unsigned g_gen;              // monotonic across replays

__device__ __forceinline__ float tanhapx(float x) {
    float y; asm("tanh.approx.f32 %0, %1;" : "=f"(y) : "f"(x)); return y;
}
__device__ __forceinline__ unsigned pack_bf16x2(float a, float b) {
    __nv_bfloat162 h = __floats2bfloat162_rn(a, b);
    return *reinterpret_cast<unsigned*>(&h);
}
__device__ __forceinline__ void ldsm_x4(unsigned& r0, unsigned& r1, unsigned& r2, unsigned& r3,
                                        unsigned saddr) {
    asm volatile("ldmatrix.sync.aligned.m8n8.x4.shared.b16 {%0,%1,%2,%3}, [%4];"
                 : "=r"(r0), "=r"(r1), "=r"(r2), "=r"(r3) : "r"(saddr));
}
__device__ __forceinline__ void ldsm_x2(unsigned& r0, unsigned& r1, unsigned saddr) {
    asm volatile("ldmatrix.sync.aligned.m8n8.x2.shared.b16 {%0,%1}, [%2];"
                 : "=r"(r0), "=r"(r1) : "r"(saddr));
}
__device__ __forceinline__ void mma16816(float* d, const unsigned* a, const unsigned* b) {
    asm volatile(
        "mma.sync.aligned.m16n8k16.row.col.f32.bf16.bf16.f32 "
        "{%0,%1,%2,%3}, {%4,%5,%6,%7}, {%8,%9}, {%0,%1,%2,%3};"
        : "+f"(d[0]), "+f"(d[1]), "+f"(d[2]), "+f"(d[3])
        : "r"(a[0]), "r"(a[1]), "r"(a[2]), "r"(a[3]), "r"(b[0]), "r"(b[1]));
}

// Device-wide barrier: generation-based, replay-safe (g_gen monotonic).
__device__ __forceinline__ void grid_barrier() {
    __syncthreads();
    if (threadIdx.x == 0) {
        __threadfence();
        unsigned gen = *((volatile unsigned*)&g_gen);
        if (atomicAdd(&g_barcnt, 1u) == NBLK - 1) {
            g_barcnt = 0;
            __threadfence();
            atomicAdd(&g_gen, 1u);
        } else {
            while (*((volatile unsigned*)&g_gen) == gen) {}
        }
    }
    __syncthreads();
}

// ---------------------------------------------------------------------------
// One GEMM unit: M=128 (2 stacked tiles), N=48, K=128, 3-pass bf16 split precision.
__device__ void do_gemm_unit(int u, char* smx,
                             const float* __restrict__ binary,
                             const float* __restrict__ unary,
                             const float* __restrict__ andk)
{
    int tid = threadIdx.x;
    bool isU = (u >= 512);

    // Stage W (48 rows x 128) hi/lo
    int o1 = isU ? 128 : 384;
    int o2 = isU ? 256 : 512;
    for (int idx = tid; idx < 48 * 32; idx += NTHR) {
        int r = idx >> 5, c4 = (idx & 31) * 4;
        int ac  = (r < 24) ? r : r - 24;
        int sg  = (r < 24) ? o1 : o2;
        float4 v = *(const float4*)(andk + (size_t)ac * NI + sg + c4);
        float hx = __bfloat162float(__float2bfloat16_rn(v.x));
        float hy = __bfloat162float(__float2bfloat16_rn(v.y));
        float hz = __bfloat162float(__float2bfloat16_rn(v.z));
        float hw = __bfloat162float(__float2bfloat16_rn(v.w));
        unsigned off = (unsigned)(r * RPITCH + c4) * 2;
        *(uint2*)(smx + S_WHI + off) = make_uint2(pack_bf16x2(v.x, v.y), pack_bf16x2(v.z, v.w));
        *(uint2*)(smx + S_WLO + off) = make_uint2(pack_bf16x2(v.x - hx, v.y - hy),
                                                 pack_bf16x2(v.z - hz, v.w - hw));
    }
    // Stage A (128 rows x 128) hi/lo
    for (int idx = tid; idx < 128 * 32; idx += NTHR) {
        int r = idx >> 5, c4 = (idx & 31) * 4;
        float4 v = make_float4(0.f, 0.f, 0.f, 0.f);
        if (isU) {
            int b = (u - 512) * 2 + (r >> 6);
            v = *(const float4*)(unary + ((size_t)b * NO + (r & 63)) * SEG + c4);
        } else {
            int t = r >> 6, k = r & 63;
            if (k < NK)
                v = *(const float4*)(binary + ((size_t)(2 * u + t) * NK + k) * SEG + c4);
        }
        float hx = __bfloat162float(__float2bfloat16_rn(v.x));
        float hy = __bfloat162float(__float2bfloat16_rn(v.y));
        float hz = __bfloat162float(__float2bfloat16_rn(v.z));
        float hw = __bfloat162float(__float2bfloat16_rn(v.w));
        unsigned off = (unsigned)(r * RPITCH + c4) * 2;
        *(uint2*)(smx + S_AHI + off) = make_uint2(pack_bf16x2(v.x, v.y), pack_bf16x2(v.z, v.w));
        *(uint2*)(smx + S_ALO + off) = make_uint2(pack_bf16x2(v.x - hx, v.y - hy),
                                                 pack_bf16x2(v.z - hz, v.w - hw));
    }
    __syncthreads();

    // 16 warps: (mg 0..7) x (ng 0..1). Warp tile m16 x n24 (3 n8 blocks).
    int wid = tid >> 5, lane = tid & 31;
    int mg = wid >> 1, ng = wid & 1;
    int c0 = ng * 24;
    float acc[3][4];
    #pragma unroll
    for (int q = 0; q < 3; q++)
        #pragma unroll
        for (int e = 0; e < 4; e++) acc[q][e] = 0.f;

    int aRow = lane & 15, aColH = lane >> 4;
    int bR16 = (lane & 7) + ((lane >> 4) << 3);
    int bC   = (lane >> 3) & 1;

    const int PA[3] = { S_AHI, S_ALO, S_AHI };
    const int PW[3] = { S_WHI, S_WHI, S_WLO };
    #pragma unroll
    for (int p = 0; p < 3; p++) {
        unsigned abase = (unsigned)__cvta_generic_to_shared(smx + PA[p]);
        unsigned wbase = (unsigned)__cvta_generic_to_shared(smx + PW[p]);
        #pragma unroll
        for (int k0 = 0; k0 < 8; k0++) {
            unsigned a[4], b[4], e2[2];
            ldsm_x4(a[0], a[1], a[2], a[3],
                    abase + ((mg * 16 + aRow) * RPITCH + k0 * 16 + aColH * 8) * 2);
            ldsm_x4(b[0], b[1], b[2], b[3],
                    wbase + ((c0 + bR16) * RPITCH + k0 * 16 + bC * 8) * 2);
            ldsm_x2(e2[0], e2[1],
                    wbase + ((c0 + 16 + (lane & 7)) * RPITCH + k0 * 16 + bC * 8) * 2);
            mma16816(acc[0], a, &b[0]);
            mma16816(acc[1], a, &b[2]);
            mma16816(acc[2], a, e2);
        }
    }
    __syncthreads();   // staging dead; reuse smem for D

    float* Dst = (float*)smx;  // 128 x DPITCH
    #pragma unroll
    for (int q = 0; q < 3; q++) {
        int rr = mg * 16 + (lane >> 2);
        int cc = c0 + q * 8 + (lane & 3) * 2;
        Dst[rr * DPITCH + cc]           = acc[q][0];
        Dst[rr * DPITCH + cc + 1]       = acc[q][1];
        Dst[(rr + 8) * DPITCH + cc]     = acc[q][2];
        Dst[(rr + 8) * DPITCH + cc + 1] = acc[q][3];
    }
    __syncthreads();

    // Coalesced write-out: 128 rows contiguous across the unit's 2 tiles.
    size_t tbase = (size_t)(isU ? 1024 + (u - 512) * 2 : 2 * u) * 64 * 48;
    int row = tid >> 2, part = tid & 3;
    #pragma unroll
    for (int s = 0; s < 3; s++) {
        float4 v = *(float4*)&Dst[row * DPITCH + part * 4 + s * 16];
        *(float4*)&g_D[tbase + row * 48 + part * 4 + s * 16] = v;
    }
    __syncthreads();
}

// ---------------------------------------------------------------------------
__global__ __launch_bounds__(NTHR, 2) void fused_kernel(
    const float* __restrict__ nullary,
    const float* __restrict__ unary,
    const float* __restrict__ binary,
    const float* __restrict__ andk,
    const float* __restrict__ ork,
    float* __restrict__ out)
{
    extern __shared__ char smx[];
    int bid = blockIdx.x;
    int tid = threadIdx.x;

    // ---- Phase 1: GEMM + setup units (static partition: bid, bid+NBLK) ----
    for (int u = bid; u < NGU; u += NBLK) {
        if (u < 520) {
            do_gemm_unit(u, smx, binary, unary, andk);
        } else if (u == 520) {
            // and_bias + or_bias
            float* sred = (float*)smx;  // 24 x 8 partials
            if (tid < 192) {
                int row = tid >> 3, part = tid & 7;
                const float* w = andk + (size_t)row * NI + part * 80;
                float s = 0.f;
                #pragma unroll 8
                for (int k = 0; k < 80; k++) { float v = w[k]; s += v * v; }
                sred[row * 8 + part] = s;
            }
            __syncthreads();
            if (tid < NAC) {
                float s = 0.f;
                #pragma unroll
                for (int p = 0; p < 8; p++) s += sred[tid * 8 + p];
                g_andbias[tid] = THRv - s * TTHR;
            } else if (tid < 27) {
                int a = tid - NAC;
                float s = 0.f;
                #pragma unroll
                for (int c = 0; c < NC; c++) { float v = ork[a * NC + c]; s += v * v; }
                g_orbias[a] = s * TTHR - THRv;
            }
            __syncthreads();
        } else {
            // DN: 384 dots of length 128
            if (tid < NB * NAC) {
                int b = tid / NAC, ac = tid % NAC;
                const float* w = andk + (size_t)ac * NI;
                const float* nv = nullary + b * SEG;
                float s = 0.f;
                #pragma unroll 8
                for (int k = 0; k < SEG; k++) s += nv[k] * w[k];
                g_DN[tid] = s;
            }
            __syncthreads();
        }
    }

    // ---- Global barrier ----
    grid_barrier();

    // ---- Phase 2: combine (blocks 0..255, 4 gi each) ----
    if (bid < 256) {
        float* base   = (float*)smx;                 // 4 x 24
        float* red    = (float*)(smx + 512);         // 4 x 64 x 17
        float* colmax = (float*)(smx + 512 + 17408); // 4 x 16
        int*   isLast = (int*)(smx + 512 + 17408 + 256);

        int tile = tid >> 7;          // 0..3
        int t2   = tid & 127;
        int k    = t2 & 63;
        int half = t2 >> 6;
        int gi = bid * 4 + tile;
        int b = gi >> 6, i = gi & 63;

        if (tid < 96) {
            int tt = tid / NAC, c = tid % NAC;
            int i2 = (bid * 4 + tt) & 63;
            base[tt * NAC + c] = g_andbias[c] + g_DN[b * NAC + c]
                               + g_D[((size_t)(1024 + b) * 64 + i2) * 48 + c];
        }
        __syncthreads();

        bool act = (k < NK);
        int j  = k + (k >= i ? 1 : 0);
        int ip = (k < i) ? (i - 1) : i;
        const float4* du1 = (const float4*)(g_D + ((size_t)(1024 + b) * 64 + j) * 48 + 24 + half * 12);
        const float4* db0 = (const float4*)(g_D + ((size_t)gi * 64 + k) * 48 + half * 12);
        const float4* db1 = (const float4*)(g_D + ((size_t)(b * 64 + j) * 64 + ip) * 48 + 24 + half * 12);

        float s[12];
        if (act) {
            #pragma unroll
            for (int q = 0; q < 3; q++) {
                float4 u  = __ldg(du1 + q);
                float4 v0 = __ldg(db0 + q);
                float4 v1 = __ldg(db1 + q);
                int cb = half * 12 + 4 * q;
                s[4 * q + 0] = base[tile * NAC + cb + 0] + u.x + v0.x + v1.x;
                s[4 * q + 1] = base[tile * NAC + cb + 1] + u.y + v0.y + v1.y;
                s[4 * q + 2] = base[tile * NAC + cb + 2] + u.z + v0.z + v1.z;
                s[4 * q + 3] = base[tile * NAC + cb + 3] + u.w + v0.w + v1.w;
            }
        }

        float* redr = red + (tile * 64 + k) * 17;
        if (half == 0) {
            #pragma unroll
            for (int c = 0; c < 12; c++)
                redr[c] = act ? tanhapx(s[c]) : -2.0f;
        } else {
            #pragma unroll
            for (int c = 0; c < 4; c++)
                redr[12 + c] = act ? tanhapx(s[c]) : -2.0f;
            if (act) {
                float s2 = g_orbias[2];
                #pragma unroll
                for (int c = 0; c < NC; c++) s2 += tanhapx(s[4 + c]) * __ldg(ork + 16 + c);
                out[16 + NB * NO + (size_t)gi * NK + k] = s2;
            }
        }
        __syncthreads();

        if (t2 < 16) {
            float m = red[(tile * 64 + 0) * 17 + t2];
            #pragma unroll 8
            for (int r = 1; r < 64; r++) m = fmaxf(m, red[(tile * 64 + r) * 17 + t2]);
            colmax[tile * 16 + t2] = m;
        }
        __syncthreads();
        if (t2 == 0) {
            float s1 = g_orbias[1];
            #pragma unroll
            for (int c = 0; c < NC; c++) s1 += colmax[tile * 16 + 8 + c] * __ldg(ork + 8 + c);
            out[16 + gi] = s1;
        }
        if (t2 < NC) g_nullpart[gi * NC + t2] = colmax[tile * 16 + t2];

        // Fused final-null reduce: last of the 16 blocks for this b.
        __syncthreads();
        if (tid == 0) {
            __threadfence();
            int v = atomicAdd(&g_cnt[b], 1);
            *isLast = (v == 15) ? 1 : 0;
        }
        __syncthreads();
        if (*isLast) {
            __threadfence();
            if (tid < NC) {
                float m = -2.0f;
                #pragma unroll 8
                for (int r = 0; r < NO; r++)
                    m = fmaxf(m, g_nullpart[(b * NO + r) * NC + tid]);
                colmax[tid] = m;
            }
            __syncthreads();
            if (tid == 0) {
                float s0 = g_orbias[0];
                #pragma unroll
                for (int c = 0; c < NC; c++) s0 += colmax[c] * __ldg(ork + c);
                out[b] = s0;
                g_cnt[b] = 0;   // reset for next graph replay
            }
        }
    }
}

// ---------------------------------------------------------------------------
extern "C" void kernel_launch(void* const* d_in, const int* in_sizes, int n_in,
                              void* d_out, int out_size)
{
    const float* nullary = (const float*)d_in[0];
    const float* unary   = (const float*)d_in[1];
    const float* binary  = (const float*)d_in[2];
    const float* andk    = (const float*)d_in[3];
    const float* ork     = (const float*)d_in[4];
    float* out = (float*)d_out;

    cudaFuncSetAttribute(fused_kernel, cudaFuncAttributeMaxDynamicSharedMemorySize, S_TOTAL);
    fused_kernel<<<NBLK, NTHR, S_TOTAL>>>(nullary, unary, binary, andk, ork, out);
}

// round 10
// speedup vs baseline: 1.3452x; 1.1649x over previous
#include <cuda_runtime.h>
#include <cuda_bf16.h>
#include <math.h>

// Problem constants
#define NB 16
#define NO 64
#define NK 63
#define NC 8
#define SEG 128
#define NI 640
#define NAC 24
#define THRv 0.2f
#define TTHR 0.19737532f   // tanh(0.2)

#define NBLK 296           // 2 per SM on 148-SM B300 (152 on GB300: safe)
#define NTHR 512
#define NGU 522            // [0,512) binary pairs, [512,520) unary, 520 bias, 521 DN

// smem layout (bytes). bf16 rows padded to 136 elems (272B, ldmatrix conflict-free)
#define RPITCH 136
#define S_AHI 0
#define S_ALO 34816
#define S_WHI 69632
#define S_WLO 82688
#define S_TOTAL 95744

// Scratch (device globals; no allocation allowed)
__device__ float g_D[1040 * 64 * 48];   // [tile][row][c]; tiles 1024+b = unary
__device__ float g_DN[NB * NAC];
__device__ float g_andbias[NAC];
__device__ float g_orbias[3];
__device__ float g_nullpart[NB * NO * NC];
__device__ int   g_cnt[NB];             // zero-init; self-resetting
__device__ unsigned g_barcnt;           // zero-init; self-resetting
__device__ unsigned g_gen;              // monotonic across replays

__device__ __forceinline__ float tanhapx(float x) {
    float y; asm("tanh.approx.f32 %0, %1;" : "=f"(y) : "f"(x)); return y;
}
__device__ __forceinline__ unsigned pack_bf16x2(float a, float b) {
    __nv_bfloat162 h = __floats2bfloat162_rn(a, b);
    return *reinterpret_cast<unsigned*>(&h);
}
__device__ __forceinline__ void ldsm_x4(unsigned& r0, unsigned& r1, unsigned& r2, unsigned& r3,
                                        unsigned saddr) {
    asm volatile("ldmatrix.sync.aligned.m8n8.x4.shared.b16 {%0,%1,%2,%3}, [%4];"
                 : "=r"(r0), "=r"(r1), "=r"(r2), "=r"(r3) : "r"(saddr));
}
__device__ __forceinline__ void ldsm_x2(unsigned& r0, unsigned& r1, unsigned saddr) {
    asm volatile("ldmatrix.sync.aligned.m8n8.x2.shared.b16 {%0,%1}, [%2];"
                 : "=r"(r0), "=r"(r1) : "r"(saddr));
}
__device__ __forceinline__ void mma16816(float* d, const unsigned* a, const unsigned* b) {
    asm volatile(
        "mma.sync.aligned.m16n8k16.row.col.f32.bf16.bf16.f32 "
        "{%0,%1,%2,%3}, {%4,%5,%6,%7}, {%8,%9}, {%0,%1,%2,%3};"
        : "+f"(d[0]), "+f"(d[1]), "+f"(d[2]), "+f"(d[3])
        : "r"(a[0]), "r"(a[1]), "r"(a[2]), "r"(a[3]), "r"(b[0]), "r"(b[1]));
}

// Device-wide barrier: generation-based, replay-safe (g_gen monotonic).
__device__ __forceinline__ void grid_barrier() {
    __syncthreads();
    if (threadIdx.x == 0) {
        __threadfence();
        unsigned gen = *((volatile unsigned*)&g_gen);
        if (atomicAdd(&g_barcnt, 1u) == NBLK - 1) {
            g_barcnt = 0;
            __threadfence();
            atomicAdd(&g_gen, 1u);
        } else {
            while (*((volatile unsigned*)&g_gen) == gen) {}
        }
    }
    __syncthreads();
}

// ---------------------------------------------------------------------------
// One GEMM unit: M=128 (2 stacked tiles), N=48, K=128.
// Single k-loop: per k0 load Ahi/Alo + Whi/Wlo fragments, 9 MMAs into one acc.
__device__ void do_gemm_unit(int u, char* smx, bool stageW,
                             const float* __restrict__ binary,
                             const float* __restrict__ unary,
                             const float* __restrict__ andk)
{
    int tid = threadIdx.x;
    bool isU = (u >= 512);

    if (stageW) {
        int o1 = isU ? 128 : 384;
        int o2 = isU ? 256 : 512;
        for (int idx = tid; idx < 48 * 32; idx += NTHR) {
            int r = idx >> 5, c4 = (idx & 31) * 4;
            int ac  = (r < 24) ? r : r - 24;
            int sg  = (r < 24) ? o1 : o2;
            float4 v = *(const float4*)(andk + (size_t)ac * NI + sg + c4);
            float hx = __bfloat162float(__float2bfloat16_rn(v.x));
            float hy = __bfloat162float(__float2bfloat16_rn(v.y));
            float hz = __bfloat162float(__float2bfloat16_rn(v.z));
            float hw = __bfloat162float(__float2bfloat16_rn(v.w));
            unsigned off = (unsigned)(r * RPITCH + c4) * 2;
            *(uint2*)(smx + S_WHI + off) = make_uint2(pack_bf16x2(v.x, v.y), pack_bf16x2(v.z, v.w));
            *(uint2*)(smx + S_WLO + off) = make_uint2(pack_bf16x2(v.x - hx, v.y - hy),
                                                     pack_bf16x2(v.z - hz, v.w - hw));
        }
    }
    // Stage A (128 rows x 128) hi/lo
    for (int idx = tid; idx < 128 * 32; idx += NTHR) {
        int r = idx >> 5, c4 = (idx & 31) * 4;
        float4 v = make_float4(0.f, 0.f, 0.f, 0.f);
        if (isU) {
            int b = (u - 512) * 2 + (r >> 6);
            v = *(const float4*)(unary + ((size_t)b * NO + (r & 63)) * SEG + c4);
        } else {
            int t = r >> 6, k = r & 63;
            if (k < NK)
                v = *(const float4*)(binary + ((size_t)(2 * u + t) * NK + k) * SEG + c4);
        }
        float hx = __bfloat162float(__float2bfloat16_rn(v.x));
        float hy = __bfloat162float(__float2bfloat16_rn(v.y));
        float hz = __bfloat162float(__float2bfloat16_rn(v.z));
        float hw = __bfloat162float(__float2bfloat16_rn(v.w));
        unsigned off = (unsigned)(r * RPITCH + c4) * 2;
        *(uint2*)(smx + S_AHI + off) = make_uint2(pack_bf16x2(v.x, v.y), pack_bf16x2(v.z, v.w));
        *(uint2*)(smx + S_ALO + off) = make_uint2(pack_bf16x2(v.x - hx, v.y - hy),
                                                 pack_bf16x2(v.z - hz, v.w - hw));
    }
    __syncthreads();

    // 16 warps: (mg 0..7) x (ng 0..1). Warp tile m16 x n24.
    int wid = tid >> 5, lane = tid & 31;
    int mg = wid >> 1, ng = wid & 1;
    int c0 = ng * 24;
    float acc[3][4];
    #pragma unroll
    for (int q = 0; q < 3; q++)
        #pragma unroll
        for (int e = 0; e < 4; e++) acc[q][e] = 0.f;

    int aRow = lane & 15, aColH = lane >> 4;
    int bR16 = (lane & 7) + ((lane >> 4) << 3);
    int bC   = (lane >> 3) & 1;

    unsigned ahb = (unsigned)__cvta_generic_to_shared(smx + S_AHI)
                 + ((mg * 16 + aRow) * RPITCH + aColH * 8) * 2;
    unsigned alb = ahb + (S_ALO - S_AHI);
    unsigned wh4 = (unsigned)__cvta_generic_to_shared(smx + S_WHI)
                 + ((c0 + bR16) * RPITCH + bC * 8) * 2;
    unsigned wh2 = (unsigned)__cvta_generic_to_shared(smx + S_WHI)
                 + ((c0 + 16 + (lane & 7)) * RPITCH + bC * 8) * 2;
    unsigned wl4 = wh4 + (S_WLO - S_WHI);
    unsigned wl2 = wh2 + (S_WLO - S_WHI);

    #pragma unroll
    for (int k0 = 0; k0 < 8; k0++) {
        unsigned koff = k0 * 32;   // 16 bf16 = 32 bytes
        unsigned ah[4], al[4], bh[6], bl[6];
        ldsm_x4(ah[0], ah[1], ah[2], ah[3], ahb + koff);
        ldsm_x4(al[0], al[1], al[2], al[3], alb + koff);
        ldsm_x4(bh[0], bh[1], bh[2], bh[3], wh4 + koff);
        ldsm_x2(bh[4], bh[5], wh2 + koff);
        ldsm_x4(bl[0], bl[1], bl[2], bl[3], wl4 + koff);
        ldsm_x2(bl[4], bl[5], wl2 + koff);
        // hi*whi
        mma16816(acc[0], ah, &bh[0]);
        mma16816(acc[1], ah, &bh[2]);
        mma16816(acc[2], ah, &bh[4]);
        // lo*whi
        mma16816(acc[0], al, &bh[0]);
        mma16816(acc[1], al, &bh[2]);
        mma16816(acc[2], al, &bh[4]);
        // hi*wlo
        mma16816(acc[0], ah, &bl[0]);
        mma16816(acc[1], ah, &bl[2]);
        mma16816(acc[2], ah, &bl[4]);
    }
    __syncthreads();   // all warps done reading smem; caller may restage

    // Direct fragment stores: D[rr][cc] -> g_D[tile(u) .. tile(u)+1][row][48]
    size_t tbase = (size_t)(isU ? 1024 + (u - 512) * 2 : 2 * u) * 64 * 48;
    int rr = mg * 16 + (lane >> 2);
    #pragma unroll
    for (int q = 0; q < 3; q++) {
        int cc = c0 + q * 8 + (lane & 3) * 2;
        *(float2*)&g_D[tbase + (size_t)rr * 48 + cc]       = make_float2(acc[q][0], acc[q][1]);
        *(float2*)&g_D[tbase + (size_t)(rr + 8) * 48 + cc] = make_float2(acc[q][2], acc[q][3]);
    }
}

// ---------------------------------------------------------------------------
__global__ __launch_bounds__(NTHR, 2) void fused_kernel(
    const float* __restrict__ nullary,
    const float* __restrict__ unary,
    const float* __restrict__ binary,
    const float* __restrict__ andk,
    const float* __restrict__ ork,
    float* __restrict__ out)
{
    extern __shared__ char smx[];
    int bid = blockIdx.x;
    int tid = threadIdx.x;

    // ---- Phase 1: GEMM + setup units (units bid, bid+NBLK) ----
    int last_wt = -1;
    for (int u = bid; u < NGU; u += NBLK) {
        if (u < 520) {
            int wt = (u >= 512) ? 1 : 0;
            do_gemm_unit(u, smx, wt != last_wt, binary, unary, andk);
            last_wt = wt;
        } else if (u == 520) {
            float* sred = (float*)smx;  // 24 x 8 partials
            if (tid < 192) {
                int row = tid >> 3, part = tid & 7;
                const float* w = andk + (size_t)row * NI + part * 80;
                float s = 0.f;
                #pragma unroll 8
                for (int k = 0; k < 80; k++) { float v = w[k]; s += v * v; }
                sred[row * 8 + part] = s;
            }
            __syncthreads();
            if (tid < NAC) {
                float s = 0.f;
                #pragma unroll
                for (int p = 0; p < 8; p++) s += sred[tid * 8 + p];
                g_andbias[tid] = THRv - s * TTHR;
            } else if (tid < 27) {
                int a = tid - NAC;
                float s = 0.f;
                #pragma unroll
                for (int c = 0; c < NC; c++) { float v = ork[a * NC + c]; s += v * v; }
                g_orbias[a] = s * TTHR - THRv;
            }
            __syncthreads();
        } else {
            if (tid < NB * NAC) {
                int b = tid / NAC, ac = tid % NAC;
                const float* w = andk + (size_t)ac * NI;
                const float* nv = nullary + b * SEG;
                float s = 0.f;
                #pragma unroll 8
                for (int k = 0; k < SEG; k++) s += nv[k] * w[k];
                g_DN[tid] = s;
            }
            __syncthreads();
        }
    }

    // ---- Global barrier ----
    grid_barrier();

    // ---- Phase 2: combine (blocks 0..255, 4 gi each) ----
    if (bid < 256) {
        float* base   = (float*)smx;                 // 4 x 24
        float* red    = (float*)(smx + 512);         // 4 x 64 x 17
        float* colmax = (float*)(smx + 512 + 17408); // 4 x 16
        int*   isLast = (int*)(smx + 512 + 17408 + 256);

        int tile = tid >> 7;          // 0..3
        int t2   = tid & 127;
        int k    = t2 & 63;
        int half = t2 >> 6;
        int gi = bid * 4 + tile;
        int b = gi >> 6, i = gi & 63;

        if (tid < 96) {
            int tt = tid / NAC, c = tid % NAC;
            int i2 = (bid * 4 + tt) & 63;
            base[tt * NAC + c] = g_andbias[c] + g_DN[b * NAC + c]
                               + g_D[((size_t)(1024 + b) * 64 + i2) * 48 + c];
        }
        __syncthreads();

        bool act = (k < NK);
        int j  = k + (k >= i ? 1 : 0);
        int ip = (k < i) ? (i - 1) : i;
        const float4* du1 = (const float4*)(g_D + ((size_t)(1024 + b) * 64 + j) * 48 + 24 + half * 12);
        const float4* db0 = (const float4*)(g_D + ((size_t)gi * 64 + k) * 48 + half * 12);
        const float4* db1 = (const float4*)(g_D + ((size_t)(b * 64 + j) * 64 + ip) * 48 + 24 + half * 12);

        float s[12];
        if (act) {
            #pragma unroll
            for (int q = 0; q < 3; q++) {
                float4 u  = __ldg(du1 + q);
                float4 v0 = __ldg(db0 + q);
                float4 v1 = __ldg(db1 + q);
                int cb = half * 12 + 4 * q;
                s[4 * q + 0] = base[tile * NAC + cb + 0] + u.x + v0.x + v1.x;
                s[4 * q + 1] = base[tile * NAC + cb + 1] + u.y + v0.y + v1.y;
                s[4 * q + 2] = base[tile * NAC + cb + 2] + u.z + v0.z + v1.z;
                s[4 * q + 3] = base[tile * NAC + cb + 3] + u.w + v0.w + v1.w;
            }
        }

        float* redr = red + (tile * 64 + k) * 17;
        if (half == 0) {
            #pragma unroll
            for (int c = 0; c < 12; c++)
                redr[c] = act ? tanhapx(s[c]) : -2.0f;
        } else {
            #pragma unroll
            for (int c = 0; c < 4; c++)
                redr[12 + c] = act ? tanhapx(s[c]) : -2.0f;
            if (act) {
                float s2 = g_orbias[2];
                #pragma unroll
                for (int c = 0; c < NC; c++) s2 += tanhapx(s[4 + c]) * __ldg(ork + 16 + c);
                out[16 + NB * NO + (size_t)gi * NK + k] = s2;
            }
        }
        __syncthreads();

        if (t2 < 16) {
            float m = red[(tile * 64 + 0) * 17 + t2];
            #pragma unroll 8
            for (int r = 1; r < 64; r++) m = fmaxf(m, red[(tile * 64 + r) * 17 + t2]);
            colmax[tile * 16 + t2] = m;
        }
        __syncthreads();
        if (t2 == 0) {
            float s1 = g_orbias[1];
            #pragma unroll
            for (int c = 0; c < NC; c++) s1 += colmax[tile * 16 + 8 + c] * __ldg(ork + 8 + c);
            out[16 + gi] = s1;
        }
        if (t2 < NC) g_nullpart[gi * NC + t2] = colmax[tile * 16 + t2];

        // Fused final-null reduce: last of the 16 blocks for this b.
        __syncthreads();
        if (tid == 0) {
            __threadfence();
            int v = atomicAdd(&g_cnt[b], 1);
            *isLast = (v == 15) ? 1 : 0;
        }
        __syncthreads();
        if (*isLast) {
            __threadfence();
            if (tid < NC) {
                float m = -2.0f;
                #pragma unroll 8
                for (int r = 0; r < NO; r++)
                    m = fmaxf(m, g_nullpart[(b * NO + r) * NC + tid]);
                colmax[tid] = m;
            }
            __syncthreads();
            if (tid == 0) {
                float s0 = g_orbias[0];
                #pragma unroll
                for (int c = 0; c < NC; c++) s0 += colmax[c] * __ldg(ork + c);
                out[b] = s0;
                g_cnt[b] = 0;   // reset for next graph replay
            }
        }
    }
}

// ---------------------------------------------------------------------------
extern "C" void kernel_launch(void* const* d_in, const int* in_sizes, int n_in,
                              void* d_out, int out_size)
{
    const float* nullary = (const float*)d_in[0];
    const float* unary   = (const float*)d_in[1];
    const float* binary  = (const float*)d_in[2];
    const float* andk    = (const float*)d_in[3];
    const float* ork     = (const float*)d_in[4];
    float* out = (float*)d_out;

    cudaFuncSetAttribute(fused_kernel, cudaFuncAttributeMaxDynamicSharedMemorySize, S_TOTAL);
    fused_kernel<<<NBLK, NTHR, S_TOTAL>>>(nullary, unary, binary, andk, ork, out);
}

// round 13
// speedup vs baseline: 1.4270x; 1.0608x over previous
#include <cuda_runtime.h>
#include <cuda_fp16.h>
#include <math.h>

// Problem constants
#define NB 16
#define NO 64
#define NK 63
#define NC 8
#define SEG 128
#define NI 640
#define NAC 24
#define THRv 0.2f
#define TTHR 0.19737532f   // tanh(0.2)

#define NBLK 296           // 2 per SM on 148-SM B300 (152 on GB300: safe)
#define NTHR 512
#define NGU 522            // [0,512) binary pairs, [512,520) unary, 520 bias, 521 DN

// smem (bytes). fp16 rows padded to 136 elems = 272B (ldmatrix conflict-free)
#define RPITCH 136
#define S_A 0
#define S_W 34816
#define S_TOTAL 47872

// Scratch (device globals; no allocation allowed)
__device__ float g_D[1040 * 64 * 48];   // [tile][row][c]; tiles 1024+b = unary
__device__ float g_DN[NB * NAC];
__device__ float g_andbias[NAC];
__device__ float g_orbias[3];
__device__ float g_nullpart[NB * NO * NC];
__device__ int   g_cnt[NB];             // zero-init; self-resetting
__device__ unsigned g_barcnt;           // zero-init; self-resetting
__device__ unsigned g_gen;              // monotonic across replays

__device__ __forceinline__ float tanhapx(float x) {
    float y; asm("tanh.approx.f32 %0, %1;" : "=f"(y) : "f"(x)); return y;
}
__device__ __forceinline__ unsigned pack_h2(float a, float b) {
    __half2 h = __floats2half2_rn(a, b);
    return *reinterpret_cast<unsigned*>(&h);
}
__device__ __forceinline__ void ldsm_x4(unsigned& r0, unsigned& r1, unsigned& r2, unsigned& r3,
                                        unsigned saddr) {
    asm volatile("ldmatrix.sync.aligned.m8n8.x4.shared.b16 {%0,%1,%2,%3}, [%4];"
                 : "=r"(r0), "=r"(r1), "=r"(r2), "=r"(r3) : "r"(saddr));
}
__device__ __forceinline__ void ldsm_x2(unsigned& r0, unsigned& r1, unsigned saddr) {
    asm volatile("ldmatrix.sync.aligned.m8n8.x2.shared.b16 {%0,%1}, [%2];"
                 : "=r"(r0), "=r"(r1) : "r"(saddr));
}
__device__ __forceinline__ void mma16816(float* d, const unsigned* a, const unsigned* b) {
    asm volatile(
        "mma.sync.aligned.m16n8k16.row.col.f32.f16.f16.f32 "
        "{%0,%1,%2,%3}, {%4,%5,%6,%7}, {%8,%9}, {%0,%1,%2,%3};"
        : "+f"(d[0]), "+f"(d[1]), "+f"(d[2]), "+f"(d[3])
        : "r"(a[0]), "r"(a[1]), "r"(a[2]), "r"(a[3]), "r"(b[0]), "r"(b[1]));
}

// Device-wide barrier: generation-based, replay-safe (g_gen monotonic).
__device__ __forceinline__ void grid_barrier() {
    __syncthreads();
    if (threadIdx.x == 0) {
        __threadfence();
        unsigned gen = *((volatile unsigned*)&g_gen);
        if (atomicAdd(&g_barcnt, 1u) == NBLK - 1) {
            g_barcnt = 0;
            __threadfence();
            atomicAdd(&g_gen, 1u);
        } else {
            while (*((volatile unsigned*)&g_gen) == gen) {}
        }
    }
    __syncthreads();
}

// ---------------------------------------------------------------------------
// One GEMM unit: M=128 (2 stacked tiles), N=48, K=128, single-pass fp16.
__device__ void do_gemm_unit(int u, char* smx, bool stageW,
                             const float* __restrict__ binary,
                             const float* __restrict__ unary,
                             const float* __restrict__ andk)
{
    int tid = threadIdx.x;
    bool isU = (u >= 512);

    if (stageW) {
        int o1 = isU ? 128 : 384;
        int o2 = isU ? 256 : 512;
        for (int idx = tid; idx < 48 * 32; idx += NTHR) {
            int r = idx >> 5, c4 = (idx & 31) * 4;
            int ac  = (r < 24) ? r : r - 24;
            int sg  = (r < 24) ? o1 : o2;
            float4 v = *(const float4*)(andk + (size_t)ac * NI + sg + c4);
            *(uint2*)(smx + S_W + (unsigned)(r * RPITCH + c4) * 2) =
                make_uint2(pack_h2(v.x, v.y), pack_h2(v.z, v.w));
        }
    }
    // Stage A (128 rows x 128) as fp16
    for (int idx = tid; idx < 128 * 32; idx += NTHR) {
        int r = idx >> 5, c4 = (idx & 31) * 4;
        float4 v = make_float4(0.f, 0.f, 0.f, 0.f);
        if (isU) {
            int b = (u - 512) * 2 + (r >> 6);
            v = *(const float4*)(unary + ((size_t)b * NO + (r & 63)) * SEG + c4);
        } else {
            int t = r >> 6, k = r & 63;
            if (k < NK)
                v = *(const float4*)(binary + ((size_t)(2 * u + t) * NK + k) * SEG + c4);
        }
        *(uint2*)(smx + S_A + (unsigned)(r * RPITCH + c4) * 2) =
            make_uint2(pack_h2(v.x, v.y), pack_h2(v.z, v.w));
    }
    __syncthreads();

    // 16 warps: (mg 0..7) x (ng 0..1). Warp tile m16 x n24.
    int wid = tid >> 5, lane = tid & 31;
    int mg = wid >> 1, ng = wid & 1;
    int c0 = ng * 24;
    float acc[3][4];
    #pragma unroll
    for (int q = 0; q < 3; q++)
        #pragma unroll
        for (int e = 0; e < 4; e++) acc[q][e] = 0.f;

    int aRow = lane & 15, aColH = lane >> 4;
    int bR16 = (lane & 7) + ((lane >> 4) << 3);
    int bC   = (lane >> 3) & 1;

    unsigned ab = (unsigned)__cvta_generic_to_shared(smx + S_A)
                + ((mg * 16 + aRow) * RPITCH + aColH * 8) * 2;
    unsigned w4 = (unsigned)__cvta_generic_to_shared(smx + S_W)
                + ((c0 + bR16) * RPITCH + bC * 8) * 2;
    unsigned w2 = (unsigned)__cvta_generic_to_shared(smx + S_W)
                + ((c0 + 16 + (lane & 7)) * RPITCH + bC * 8) * 2;

    #pragma unroll
    for (int k0 = 0; k0 < 8; k0++) {
        unsigned koff = k0 * 32;   // 16 fp16 = 32 bytes
        unsigned a[4], b[6];
        ldsm_x4(a[0], a[1], a[2], a[3], ab + koff);
        ldsm_x4(b[0], b[1], b[2], b[3], w4 + koff);
        ldsm_x2(b[4], b[5], w2 + koff);
        mma16816(acc[0], a, &b[0]);
        mma16816(acc[1], a, &b[2]);
        mma16816(acc[2], a, &b[4]);
    }

    // Epilogue: direct fragment stores to g_D (2 tiles of the unit)
    size_t tbase = (size_t)(isU ? 1024 + (u - 512) * 2 : 2 * u) * 64 * 48;
    int rr = mg * 16 + (lane >> 2);
    #pragma unroll
    for (int q = 0; q < 3; q++) {
        int cc = c0 + q * 8 + (lane & 3) * 2;
        *(float2*)&g_D[tbase + (size_t)rr * 48 + cc]       = make_float2(acc[q][0], acc[q][1]);
        *(float2*)&g_D[tbase + (size_t)(rr + 8) * 48 + cc] = make_float2(acc[q][2], acc[q][3]);
    }
    __syncthreads();   // all warps done reading smem; caller may restage
}

// ---------------------------------------------------------------------------
__global__ __launch_bounds__(NTHR, 2) void fused_kernel(
    const float* __restrict__ nullary,
    const float* __restrict__ unary,
    const float* __restrict__ binary,
    const float* __restrict__ andk,
    const float* __restrict__ ork,
    float* __restrict__ out)
{
    extern __shared__ char smx[];
    int bid = blockIdx.x;
    int tid = threadIdx.x;

    // ---- Phase 1: GEMM + setup units (units bid, bid+NBLK) ----
    int last_wt = -1;
    for (int u = bid; u < NGU; u += NBLK) {
        if (u < 520) {
            int wt = (u >= 512) ? 1 : 0;
            do_gemm_unit(u, smx, wt != last_wt, binary, unary, andk);
            last_wt = wt;
        } else if (u == 520) {
            float* sred = (float*)smx;  // 24 x 8 partials
            if (tid < 192) {
                int row = tid >> 3, part = tid & 7;
                const float* w = andk + (size_t)row * NI + part * 80;
                float s = 0.f;
                #pragma unroll 8
                for (int k = 0; k < 80; k++) { float v = w[k]; s += v * v; }
                sred[row * 8 + part] = s;
            }
            __syncthreads();
            if (tid < NAC) {
                float s = 0.f;
                #pragma unroll
                for (int p = 0; p < 8; p++) s += sred[tid * 8 + p];
                g_andbias[tid] = THRv - s * TTHR;
            } else if (tid < 27) {
                int a = tid - NAC;
                float s = 0.f;
                #pragma unroll
                for (int c = 0; c < NC; c++) { float v = ork[a * NC + c]; s += v * v; }
                g_orbias[a] = s * TTHR - THRv;
            }
            __syncthreads();
        } else {
            if (tid < NB * NAC) {
                int b = tid / NAC, ac = tid % NAC;
                const float* w = andk + (size_t)ac * NI;
                const float* nv = nullary + b * SEG;
                float s = 0.f;
                #pragma unroll 8
                for (int k = 0; k < SEG; k++) s += nv[k] * w[k];
                g_DN[tid] = s;
            }
            __syncthreads();
        }
    }

    // ---- Global barrier ----
    grid_barrier();

    // ---- Phase 2: combine (blocks 0..255, 4 gi each) ----
    if (bid < 256) {
        float* base   = (float*)smx;                 // 4 x 24
        float* red    = (float*)(smx + 512);         // 4 x 64 x 17
        float* colmax = (float*)(smx + 512 + 17408); // 4 x 16
        int*   isLast = (int*)(smx + 512 + 17408 + 256);

        int tile = tid >> 7;          // 0..3
        int t2   = tid & 127;
        int k    = t2 & 63;
        int half = t2 >> 6;
        int gi = bid * 4 + tile;
        int b = gi >> 6, i = gi & 63;

        if (tid < 96) {
            int tt = tid / NAC, c = tid % NAC;
            int i2 = (bid * 4 + tt) & 63;
            base[tt * NAC + c] = g_andbias[c] + g_DN[b * NAC + c]
                               + g_D[((size_t)(1024 + b) * 64 + i2) * 48 + c];
        }
        __syncthreads();

        bool act = (k < NK);
        int j  = k + (k >= i ? 1 : 0);
        int ip = (k < i) ? (i - 1) : i;
        const float4* du1 = (const float4*)(g_D + ((size_t)(1024 + b) * 64 + j) * 48 + 24 + half * 12);
        const float4* db0 = (const float4*)(g_D + ((size_t)gi * 64 + k) * 48 + half * 12);
        const float4* db1 = (const float4*)(g_D + ((size_t)(b * 64 + j) * 64 + ip) * 48 + 24 + half * 12);

        float s[12];
        if (act) {
            #pragma unroll
            for (int q = 0; q < 3; q++) {
                float4 u  = __ldg(du1 + q);
                float4 v0 = __ldg(db0 + q);
                float4 v1 = __ldg(db1 + q);
                int cb = half * 12 + 4 * q;
                s[4 * q + 0] = base[tile * NAC + cb + 0] + u.x + v0.x + v1.x;
                s[4 * q + 1] = base[tile * NAC + cb + 1] + u.y + v0.y + v1.y;
                s[4 * q + 2] = base[tile * NAC + cb + 2] + u.z + v0.z + v1.z;
                s[4 * q + 3] = base[tile * NAC + cb + 3] + u.w + v0.w + v1.w;
            }
        }

        float* redr = red + (tile * 64 + k) * 17;
        if (half == 0) {
            #pragma unroll
            for (int c = 0; c < 12; c++)
                redr[c] = act ? tanhapx(s[c]) : -2.0f;
        } else {
            #pragma unroll
            for (int c = 0; c < 4; c++)
                redr[12 + c] = act ? tanhapx(s[c]) : -2.0f;
            if (act) {
                float s2 = g_orbias[2];
                #pragma unroll
                for (int c = 0; c < NC; c++) s2 += tanhapx(s[4 + c]) * __ldg(ork + 16 + c);
                out[16 + NB * NO + (size_t)gi * NK + k] = s2;
            }
        }
        __syncthreads();

        if (t2 < 16) {
            float m = red[(tile * 64 + 0) * 17 + t2];
            #pragma unroll 8
            for (int r = 1; r < 64; r++) m = fmaxf(m, red[(tile * 64 + r) * 17 + t2]);
            colmax[tile * 16 + t2] = m;
        }
        __syncthreads();
        if (t2 == 0) {
            float s1 = g_orbias[1];
            #pragma unroll
            for (int c = 0; c < NC; c++) s1 += colmax[tile * 16 + 8 + c] * __ldg(ork + 8 + c);
            out[16 + gi] = s1;
        }
        if (t2 < NC) g_nullpart[gi * NC + t2] = colmax[tile * 16 + t2];

        // Fused final-null reduce: last of the 16 blocks for this b.
        __syncthreads();
        if (tid == 0) {
            __threadfence();
            int v = atomicAdd(&g_cnt[b], 1);
            *isLast = (v == 15) ? 1 : 0;
        }
        __syncthreads();
        if (*isLast) {
            __threadfence();
            if (tid < NC) {
                float m = -2.0f;
                #pragma unroll 8
                for (int r = 0; r < NO; r++)
                    m = fmaxf(m, g_nullpart[(b * NO + r) * NC + tid]);
                colmax[tid] = m;
            }
            __syncthreads();
            if (tid == 0) {
                float s0 = g_orbias[0];
                #pragma unroll
                for (int c = 0; c < NC; c++) s0 += colmax[c] * __ldg(ork + c);
                out[b] = s0;
                g_cnt[b] = 0;   // reset for next graph replay
            }
        }
    }
}

// ---------------------------------------------------------------------------
extern "C" void kernel_launch(void* const* d_in, const int* in_sizes, int n_in,
                              void* d_out, int out_size)
{
    const float* nullary = (const float*)d_in[0];
    const float* unary   = (const float*)d_in[1];
    const float* binary  = (const float*)d_in[2];
    const float* andk    = (const float*)d_in[3];
    const float* ork     = (const float*)d_in[4];
    float* out = (float*)d_out;

    cudaFuncSetAttribute(fused_kernel, cudaFuncAttributeMaxDynamicSharedMemorySize, S_TOTAL);
    fused_kernel<<<NBLK, NTHR, S_TOTAL>>>(nullary, unary, binary, andk, ork, out);
}

// round 14
// speedup vs baseline: 1.4355x; 1.0060x over previous
#include <cuda_runtime.h>
#include <cuda_fp16.h>
#include <math.h>

// Problem constants
#define NB 16
#define NO 64
#define NK 63
#define NC 8
#define SEG 128
#define NI 640
#define NAC 24
#define THRv 0.2f
#define TTHR 0.19737532f   // tanh(0.2)

#define NBLK 148           // 1 per SM (148 on B300, 152 on GB300)
#define NTHR 1024

// smem layout (bytes)
#define RPITCH 136         // fp16 row pitch (elems); 272B, ldmatrix conflict-free
#define S_RAW0 0           // raw f32 tile buffer 0: 128 rows x 512B = 65536
#define S_RAW1 65536       // raw f32 tile buffer 1
#define S_A    131072      // fp16 A: 128 x RPITCH x 2 = 34816
#define S_W    165888      // fp16 W: 48 x RPITCH x 2 = 13056
#define S_TOTAL 178944

// Scratch (device globals; no allocation allowed)
__device__ float g_D[1040 * 64 * 48];   // [tile][row][c]; tiles 1024+b = unary
__device__ float g_DN[NB * NAC];
__device__ float g_andbias[NAC];
__device__ float g_orbias[3];
__device__ float g_nullpart[NB * NO * NC];
__device__ int   g_cnt[NB];             // zero-init; self-resetting
__device__ unsigned g_barcnt;           // zero-init; self-resetting
__device__ unsigned g_gen;              // monotonic across replays

__device__ __forceinline__ float tanhapx(float x) {
    float y; asm("tanh.approx.f32 %0, %1;" : "=f"(y) : "f"(x)); return y;
}
__device__ __forceinline__ unsigned pack_h2(float a, float b) {
    __half2 h = __floats2half2_rn(a, b);
    return *reinterpret_cast<unsigned*>(&h);
}
__device__ __forceinline__ void cpasync16(void* sdst, const void* gsrc) {
    unsigned s = (unsigned)__cvta_generic_to_shared(sdst);
    asm volatile("cp.async.cg.shared.global [%0], [%1], 16;" :: "r"(s), "l"(gsrc));
}
__device__ __forceinline__ void ldsm_x4(unsigned& r0, unsigned& r1, unsigned& r2, unsigned& r3,
                                        unsigned saddr) {
    asm volatile("ldmatrix.sync.aligned.m8n8.x4.shared.b16 {%0,%1,%2,%3}, [%4];"
                 : "=r"(r0), "=r"(r1), "=r"(r2), "=r"(r3) : "r"(saddr));
}
__device__ __forceinline__ void ldsm_x2(unsigned& r0, unsigned& r1, unsigned saddr) {
    asm volatile("ldmatrix.sync.aligned.m8n8.x2.shared.b16 {%0,%1}, [%2];"
                 : "=r"(r0), "=r"(r1) : "r"(saddr));
}
__device__ __forceinline__ void mma16816(float* d, const unsigned* a, const unsigned* b) {
    asm volatile(
        "mma.sync.aligned.m16n8k16.row.col.f32.f16.f16.f32 "
        "{%0,%1,%2,%3}, {%4,%5,%6,%7}, {%8,%9}, {%0,%1,%2,%3};"
        : "+f"(d[0]), "+f"(d[1]), "+f"(d[2]), "+f"(d[3])
        : "r"(a[0]), "r"(a[1]), "r"(a[2]), "r"(a[3]), "r"(b[0]), "r"(b[1]));
}

// Device-wide barrier: generation-based, replay-safe (g_gen monotonic).
__device__ __forceinline__ void grid_barrier() {
    __syncthreads();
    if (threadIdx.x == 0) {
        __threadfence();
        unsigned gen = *((volatile unsigned*)&g_gen);
        if (atomicAdd(&g_barcnt, 1u) == NBLK - 1) {
            g_barcnt = 0;
            __threadfence();
            atomicAdd(&g_gen, 1u);
        } else {
            while (*((volatile unsigned*)&g_gen) == gen) {}
        }
    }
    __syncthreads();
}

// ---------------------------------------------------------------------------
// Issue cp.async for unit u into raw buffer buf. Rows 63/127 of binary tiles
// are pre-zeroed and never written.
__device__ __forceinline__ void cp_issue_unit(int u, char* smx, int buf,
                                              const float* __restrict__ binary,
                                              const float* __restrict__ unary)
{
    int tid = threadIdx.x;
    char* dst = smx + (buf ? S_RAW1 : S_RAW0);
    if (u >= 512) {
        #pragma unroll
        for (int it = 0; it < 4; it++) {
            int idx = tid + it * NTHR;              // 0..4095 (16B granules)
            int r = idx >> 5, c4 = (idx & 31) * 4;
            int b = (u - 512) * 2 + (r >> 6);
            cpasync16(dst + idx * 16, unary + ((size_t)b * NO + (r & 63)) * SEG + c4);
        }
    } else {
        #pragma unroll
        for (int it = 0; it < 4; it++) {
            int idx = tid + it * NTHR;
            int r = idx >> 5, c4 = (idx & 31) * 4;
            int t = r >> 6, k = r & 63;
            if (k < NK)
                cpasync16(dst + idx * 16, binary + ((size_t)(2 * u + t) * NK + k) * SEG + c4);
        }
    }
    asm volatile("cp.async.commit_group;");
}

// Convert raw f32 buffer -> fp16 A staging.
__device__ __forceinline__ void convert_unit(char* smx, int buf) {
    int tid = threadIdx.x;
    const char* src = smx + (buf ? S_RAW1 : S_RAW0);
    #pragma unroll
    for (int it = 0; it < 4; it++) {
        int idx = tid + it * NTHR;
        int r = idx >> 5, c4 = (idx & 31) * 4;
        float4 v = *(const float4*)(src + idx * 16);
        *(uint2*)(smx + S_A + (unsigned)(r * RPITCH + c4) * 2) =
            make_uint2(pack_h2(v.x, v.y), pack_h2(v.z, v.w));
    }
}

// Stage W (48 rows x 128) from gmem as fp16.
__device__ __forceinline__ void stage_W(char* smx, bool isU, const float* __restrict__ andk) {
    int tid = threadIdx.x;
    int o1 = isU ? 128 : 384;
    int o2 = isU ? 256 : 512;
    for (int idx = tid; idx < 48 * 32; idx += NTHR) {
        int r = idx >> 5, c4 = (idx & 31) * 4;
        int ac  = (r < 24) ? r : r - 24;
        int sg  = (r < 24) ? o1 : o2;
        float4 v = *(const float4*)(andk + (size_t)ac * NI + sg + c4);
        *(uint2*)(smx + S_W + (unsigned)(r * RPITCH + c4) * 2) =
            make_uint2(pack_h2(v.x, v.y), pack_h2(v.z, v.w));
    }
}

// mma (warps 0..15) + direct epilogue stores for unit u.
__device__ __forceinline__ void mma_and_store(char* smx, int u) {
    int tid = threadIdx.x;
    int wid = tid >> 5, lane = tid & 31;
    if (wid >= 16) return;
    int mg = wid >> 1, ng = wid & 1;
    int c0 = ng * 24;
    float acc[3][4];
    #pragma unroll
    for (int q = 0; q < 3; q++)
        #pragma unroll
        for (int e = 0; e < 4; e++) acc[q][e] = 0.f;

    int aRow = lane & 15, aColH = lane >> 4;
    int bR16 = (lane & 7) + ((lane >> 4) << 3);
    int bC   = (lane >> 3) & 1;

    unsigned ab = (unsigned)__cvta_generic_to_shared(smx + S_A)
                + ((mg * 16 + aRow) * RPITCH + aColH * 8) * 2;
    unsigned w4 = (unsigned)__cvta_generic_to_shared(smx + S_W)
                + ((c0 + bR16) * RPITCH + bC * 8) * 2;
    unsigned w2 = (unsigned)__cvta_generic_to_shared(smx + S_W)
                + ((c0 + 16 + (lane & 7)) * RPITCH + bC * 8) * 2;

    #pragma unroll
    for (int k0 = 0; k0 < 8; k0++) {
        unsigned koff = k0 * 32;
        unsigned a[4], b[6];
        ldsm_x4(a[0], a[1], a[2], a[3], ab + koff);
        ldsm_x4(b[0], b[1], b[2], b[3], w4 + koff);
        ldsm_x2(b[4], b[5], w2 + koff);
        mma16816(acc[0], a, &b[0]);
        mma16816(acc[1], a, &b[2]);
        mma16816(acc[2], a, &b[4]);
    }

    bool isU = (u >= 512);
    size_t tbase = (size_t)(isU ? 1024 + (u - 512) * 2 : 2 * u) * 64 * 48;
    int rr = mg * 16 + (lane >> 2);
    #pragma unroll
    for (int q = 0; q < 3; q++) {
        int cc = c0 + q * 8 + (lane & 3) * 2;
        *(float2*)&g_D[tbase + (size_t)rr * 48 + cc]       = make_float2(acc[q][0], acc[q][1]);
        *(float2*)&g_D[tbase + (size_t)(rr + 8) * 48 + cc] = make_float2(acc[q][2], acc[q][3]);
    }
}

// ---------------------------------------------------------------------------
__global__ __launch_bounds__(NTHR, 1) void fused_kernel(
    const float* __restrict__ nullary,
    const float* __restrict__ unary,
    const float* __restrict__ binary,
    const float* __restrict__ andk,
    const float* __restrict__ ork,
    float* __restrict__ out)
{
    extern __shared__ char smx[];
    int bid = blockIdx.x;
    int tid = threadIdx.x;

    // Zero pad rows (63, 127) of both raw buffers (binary tiles never write them).
    if (tid < 128) {
        int which = tid >> 5;
        int off = (tid & 31) * 16;
        char* p = smx + ((which & 2) ? S_RAW1 : S_RAW0) + ((which & 1) ? 127 : 63) * 512 + off;
        *(float4*)p = make_float4(0.f, 0.f, 0.f, 0.f);
    }

    // GEMM unit list for this block (ascending; unary last if present)
    int ulist[4]; int n = 0;
    for (int u = bid; u < 520; u += NBLK) ulist[n++] = u;

    // ---- Phase 1: cp.async double-buffered GEMM pipeline ----
    cp_issue_unit(ulist[0], smx, 0, binary, unary);
    int last_wt = -1;
    for (int i = 0; i < n; i++) {
        if (i + 1 < n) {
            cp_issue_unit(ulist[i + 1], smx, (i + 1) & 1, binary, unary);
            asm volatile("cp.async.wait_group 1;");
        } else {
            asm volatile("cp.async.wait_group 0;");
        }
        __syncthreads();
        int wt = (ulist[i] >= 512) ? 1 : 0;
        if (wt != last_wt) { stage_W(smx, wt != 0, andk); last_wt = wt; }
        convert_unit(smx, i & 1);
        __syncthreads();
        mma_and_store(smx, ulist[i]);
    }

    // ---- Setup units (blocks 76: biases, 77: DN) ----
    if (bid == 76) {
        __syncthreads();
        float* sred = (float*)smx;  // 24 x 8 partials (raw0 area, now dead)
        if (tid < 192) {
            int row = tid >> 3, part = tid & 7;
            const float* w = andk + (size_t)row * NI + part * 80;
            float s = 0.f;
            #pragma unroll 8
            for (int k = 0; k < 80; k++) { float v = w[k]; s += v * v; }
            sred[row * 8 + part] = s;
        }
        __syncthreads();
        if (tid < NAC) {
            float s = 0.f;
            #pragma unroll
            for (int p = 0; p < 8; p++) s += sred[tid * 8 + p];
            g_andbias[tid] = THRv - s * TTHR;
        } else if (tid < 27) {
            int a = tid - NAC;
            float s = 0.f;
            #pragma unroll
            for (int c = 0; c < NC; c++) { float v = ork[a * NC + c]; s += v * v; }
            g_orbias[a] = s * TTHR - THRv;
        }
    } else if (bid == 77) {
        if (tid < NB * NAC) {
            int b = tid / NAC, ac = tid % NAC;
            const float* w = andk + (size_t)ac * NI;
            const float* nv = nullary + b * SEG;
            float s = 0.f;
            #pragma unroll 8
            for (int k = 0; k < SEG; k++) s += nv[k] * w[k];
            g_DN[tid] = s;
        }
    }

    // ---- Global barrier ----
    grid_barrier();

    // ---- Phase 2: combine (blocks 0..127, 8 gi each) ----
    if (bid < 128) {
        float* base   = (float*)smx;                   // 8 x 24
        float* red    = (float*)(smx + 1024);          // 8 x 64 x 17
        float* colmax = (float*)(smx + 1024 + 34816);  // 8 x 16
        int*   isLast = (int*)(smx + 1024 + 34816 + 512);

        int tile = tid >> 7;          // 0..7
        int t2   = tid & 127;
        int k    = t2 & 63;
        int half = t2 >> 6;
        int gi = bid * 8 + tile;
        int b = bid >> 3;             // uniform per block
        int i = gi & 63;

        if (tid < 192) {
            int tt = tid / NAC, c = tid % NAC;
            int i2 = (bid * 8 + tt) & 63;
            base[tt * NAC + c] = g_andbias[c] + g_DN[b * NAC + c]
                               + g_D[((size_t)(1024 + b) * 64 + i2) * 48 + c];
        }
        __syncthreads();

        bool act = (k < NK);
        int j  = k + (k >= i ? 1 : 0);
        int ip = (k < i) ? (i - 1) : i;
        const float4* du1 = (const float4*)(g_D + ((size_t)(1024 + b) * 64 + j) * 48 + 24 + half * 12);
        const float4* db0 = (const float4*)(g_D + ((size_t)gi * 64 + k) * 48 + half * 12);
        const float4* db1 = (const float4*)(g_D + ((size_t)(b * 64 + j) * 64 + ip) * 48 + 24 + half * 12);

        float s[12];
        if (act) {
            #pragma unroll
            for (int q = 0; q < 3; q++) {
                float4 u  = __ldg(du1 + q);
                float4 v0 = __ldg(db0 + q);
                float4 v1 = __ldg(db1 + q);
                int cb = half * 12 + 4 * q;
                s[4 * q + 0] = base[tile * NAC + cb + 0] + u.x + v0.x + v1.x;
                s[4 * q + 1] = base[tile * NAC + cb + 1] + u.y + v0.y + v1.y;
                s[4 * q + 2] = base[tile * NAC + cb + 2] + u.z + v0.z + v1.z;
                s[4 * q + 3] = base[tile * NAC + cb + 3] + u.w + v0.w + v1.w;
            }
        }

        float* redr = red + (tile * 64 + k) * 17;
        if (half == 0) {
            #pragma unroll
            for (int c = 0; c < 12; c++)
                redr[c] = act ? tanhapx(s[c]) : -2.0f;
        } else {
            #pragma unroll
            for (int c = 0; c < 4; c++)
                redr[12 + c] = act ? tanhapx(s[c]) : -2.0f;
            if (act) {
                float s2 = g_orbias[2];
                #pragma unroll
                for (int c = 0; c < NC; c++) s2 += tanhapx(s[4 + c]) * __ldg(ork + 16 + c);
                out[16 + NB * NO + (size_t)gi * NK + k] = s2;
            }
        }
        __syncthreads();

        if (t2 < 16) {
            float m = red[(tile * 64 + 0) * 17 + t2];
            #pragma unroll 8
            for (int r = 1; r < 64; r++) m = fmaxf(m, red[(tile * 64 + r) * 17 + t2]);
            colmax[tile * 16 + t2] = m;
        }
        __syncthreads();
        if (t2 == 0) {
            float s1 = g_orbias[1];
            #pragma unroll
            for (int c = 0; c < NC; c++) s1 += colmax[tile * 16 + 8 + c] * __ldg(ork + 8 + c);
            out[16 + gi] = s1;
        }
        if (t2 < NC) g_nullpart[gi * NC + t2] = colmax[tile * 16 + t2];

        // Fused final-null reduce: last of the 8 blocks for this b.
        __syncthreads();
        if (tid == 0) {
            __threadfence();
            int v = atomicAdd(&g_cnt[b], 1);
            *isLast = (v == 7) ? 1 : 0;
        }
        __syncthreads();
        if (*isLast) {
            __threadfence();
            if (tid < NC) {
                float m = -2.0f;
                #pragma unroll 8
                for (int r = 0; r < NO; r++)
                    m = fmaxf(m, g_nullpart[(b * NO + r) * NC + tid]);
                colmax[tid] = m;
            }
            __syncthreads();
            if (tid == 0) {
                float s0 = g_orbias[0];
                #pragma unroll
                for (int c = 0; c < NC; c++) s0 += colmax[c] * __ldg(ork + c);
                out[b] = s0;
                g_cnt[b] = 0;   // reset for next graph replay
            }
        }
    }
}

// ---------------------------------------------------------------------------
extern "C" void kernel_launch(void* const* d_in, const int* in_sizes, int n_in,
                              void* d_out, int out_size)
{
    const float* nullary = (const float*)d_in[0];
    const float* unary   = (const float*)d_in[1];
    const float* binary  = (const float*)d_in[2];
    const float* andk    = (const float*)d_in[3];
    const float* ork     = (const float*)d_in[4];
    float* out = (float*)d_out;

    cudaFuncSetAttribute(fused_kernel, cudaFuncAttributeMaxDynamicSharedMemorySize, S_TOTAL);
    fused_kernel<<<NBLK, NTHR, S_TOTAL>>>(nullary, unary, binary, andk, ork, out);
}

// round 16
// speedup vs baseline: 1.4865x; 1.0355x over previous
#include <cuda_runtime.h>
#include <cuda_fp16.h>
#include <math.h>

// Problem constants
#define NB 16
#define NO 64
#define NK 63
#define NC 8
#define SEG 128
#define NI 640
#define NAC 24
#define THRv 0.2f
#define TTHR 0.19737532f   // tanh(0.2)

#define NBLK 148           // 1 per SM (148 on B300, 152 on GB300)
#define NTHR 1024

// smem layout (bytes). fp16 rows padded to 136 elems (272B, ldmatrix conflict-free)
#define RPITCH 136
#define S_A0 0             // fp16 A buffer 0: 128 x RPITCH x 2 = 34816
#define S_A1 34816         // fp16 A buffer 1
#define S_WB 69632         // fp16 W binary: 48 x RPITCH x 2 = 13056
#define S_WU 82688         // fp16 W unary
#define S_TOTAL 95744

// Scratch (device globals; no allocation allowed)
__device__ float g_D[1040 * 64 * 48];   // [tile][row][c]; tiles 1024+b = unary
__device__ float g_DN[NB * NAC];
__device__ float g_andbias[NAC];
__device__ float g_orbias[3];
__device__ float g_nullpart[NB * NO * NC];
__device__ int   g_cnt[NB];             // zero-init; self-resetting
__device__ unsigned g_barcnt;           // zero-init; self-resetting
__device__ unsigned g_gen;              // monotonic across replays

__device__ __forceinline__ float tanhapx(float x) {
    float y; asm("tanh.approx.f32 %0, %1;" : "=f"(y) : "f"(x)); return y;
}
__device__ __forceinline__ unsigned pack_h2(float a, float b) {
    __half2 h = __floats2half2_rn(a, b);
    return *reinterpret_cast<unsigned*>(&h);
}
__device__ __forceinline__ void ldsm_x4(unsigned& r0, unsigned& r1, unsigned& r2, unsigned& r3,
                                        unsigned saddr) {
    asm volatile("ldmatrix.sync.aligned.m8n8.x4.shared.b16 {%0,%1,%2,%3}, [%4];"
                 : "=r"(r0), "=r"(r1), "=r"(r2), "=r"(r3) : "r"(saddr));
}
__device__ __forceinline__ void ldsm_x2(unsigned& r0, unsigned& r1, unsigned saddr) {
    asm volatile("ldmatrix.sync.aligned.m8n8.x2.shared.b16 {%0,%1}, [%2];"
                 : "=r"(r0), "=r"(r1) : "r"(saddr));
}
__device__ __forceinline__ void mma16816(float* d, const unsigned* a, const unsigned* b) {
    asm volatile(
        "mma.sync.aligned.m16n8k16.row.col.f32.f16.f16.f32 "
        "{%0,%1,%2,%3}, {%4,%5,%6,%7}, {%8,%9}, {%0,%1,%2,%3};"
        : "+f"(d[0]), "+f"(d[1]), "+f"(d[2]), "+f"(d[3])
        : "r"(a[0]), "r"(a[1]), "r"(a[2]), "r"(a[3]), "r"(b[0]), "r"(b[1]));
}

// Device-wide barrier: generation-based, replay-safe (g_gen monotonic).
__device__ __forceinline__ void grid_barrier() {
    __syncthreads();
    if (threadIdx.x == 0) {
        __threadfence();
        unsigned gen = *((volatile unsigned*)&g_gen);
        if (atomicAdd(&g_barcnt, 1u) == NBLK - 1) {
            g_barcnt = 0;
            __threadfence();
            atomicAdd(&g_gen, 1u);
        } else {
            while (*((volatile unsigned*)&g_gen) == gen) {}
        }
    }
    __syncthreads();
}

// ---------------------------------------------------------------------------
// Producer (threads 512..1023): load unit u (128 rows x 128 f32), convert to
// fp16, store into A buffer buf. LDGs batched in regs for full MLP.
__device__ __forceinline__ void produce_unit(int u, char* smx, int buf,
                                             const float* __restrict__ binary,
                                             const float* __restrict__ unary)
{
    int t2 = threadIdx.x - 512;           // 0..511
    char* dst = smx + (buf ? S_A1 : S_A0);
    float4 v[8];
    if (u >= 512) {
        #pragma unroll
        for (int it = 0; it < 8; it++) {
            int g = t2 + it * 512;
            int r = g >> 5, c4 = (g & 31) * 4;
            int b = (u - 512) * 2 + (r >> 6);
            v[it] = *(const float4*)(unary + ((size_t)b * NO + (r & 63)) * SEG + c4);
        }
    } else {
        #pragma unroll
        for (int it = 0; it < 8; it++) {
            int g = t2 + it * 512;
            int r = g >> 5, c4 = (g & 31) * 4;
            int t = r >> 6, k = r & 63;
            v[it] = (k < NK)
                ? *(const float4*)(binary + ((size_t)(2 * u + t) * NK + k) * SEG + c4)
                : make_float4(0.f, 0.f, 0.f, 0.f);
        }
    }
    #pragma unroll
    for (int it = 0; it < 8; it++) {
        int g = t2 + it * 512;
        int r = g >> 5, c4 = (g & 31) * 4;
        *(uint2*)(dst + (unsigned)(r * RPITCH + c4) * 2) =
            make_uint2(pack_h2(v[it].x, v[it].y), pack_h2(v[it].z, v[it].w));
    }
}

// Producer prologue: stage both W matrices (binary + unary) as fp16.
__device__ __forceinline__ void stage_both_W(char* smx, const float* __restrict__ andk) {
    int t2 = threadIdx.x - 512;
    #pragma unroll
    for (int it = 0; it < 3; it++) {
        int idx = t2 + it * 512;          // 0..1535
        int r = idx >> 5, c4 = (idx & 31) * 4;
        int ac = (r < 24) ? r : r - 24;
        // binary: segments 384 / 512
        float4 vb = *(const float4*)(andk + (size_t)ac * NI + ((r < 24) ? 384 : 512) + c4);
        *(uint2*)(smx + S_WB + (unsigned)(r * RPITCH + c4) * 2) =
            make_uint2(pack_h2(vb.x, vb.y), pack_h2(vb.z, vb.w));
        // unary: segments 128 / 256
        float4 vu = *(const float4*)(andk + (size_t)ac * NI + ((r < 24) ? 128 : 256) + c4);
        *(uint2*)(smx + S_WU + (unsigned)(r * RPITCH + c4) * 2) =
            make_uint2(pack_h2(vu.x, vu.y), pack_h2(vu.z, vu.w));
    }
}

// Consumer (threads 0..511 = warps 0..15): mma + direct epilogue stores.
__device__ __forceinline__ void mma_and_store(char* smx, int buf, int u) {
    int tid = threadIdx.x;
    int wid = tid >> 5, lane = tid & 31;
    int mg = wid >> 1, ng = wid & 1;
    int c0 = ng * 24;
    float acc[3][4];
    #pragma unroll
    for (int q = 0; q < 3; q++)
        #pragma unroll
        for (int e = 0; e < 4; e++) acc[q][e] = 0.f;

    int aRow = lane & 15, aColH = lane >> 4;
    int bR16 = (lane & 7) + ((lane >> 4) << 3);
    int bC   = (lane >> 3) & 1;

    unsigned wsel = (u >= 512) ? S_WU : S_WB;
    unsigned ab = (unsigned)__cvta_generic_to_shared(smx + (buf ? S_A1 : S_A0))
                + ((mg * 16 + aRow) * RPITCH + aColH * 8) * 2;
    unsigned w4 = (unsigned)__cvta_generic_to_shared(smx + wsel)
                + ((c0 + bR16) * RPITCH + bC * 8) * 2;
    unsigned w2 = (unsigned)__cvta_generic_to_shared(smx + wsel)
                + ((c0 + 16 + (lane & 7)) * RPITCH + bC * 8) * 2;

    #pragma unroll
    for (int k0 = 0; k0 < 8; k0++) {
        unsigned koff = k0 * 32;
        unsigned a[4], b[6];
        ldsm_x4(a[0], a[1], a[2], a[3], ab + koff);
        ldsm_x4(b[0], b[1], b[2], b[3], w4 + koff);
        ldsm_x2(b[4], b[5], w2 + koff);
        mma16816(acc[0], a, &b[0]);
        mma16816(acc[1], a, &b[2]);
        mma16816(acc[2], a, &b[4]);
    }

    bool isU = (u >= 512);
    size_t tbase = (size_t)(isU ? 1024 + (u - 512) * 2 : 2 * u) * 64 * 48;
    int rr = mg * 16 + (lane >> 2);
    #pragma unroll
    for (int q = 0; q < 3; q++) {
        int cc = c0 + q * 8 + (lane & 3) * 2;
        *(float2*)&g_D[tbase + (size_t)rr * 48 + cc]       = make_float2(acc[q][0], acc[q][1]);
        *(float2*)&g_D[tbase + (size_t)(rr + 8) * 48 + cc] = make_float2(acc[q][2], acc[q][3]);
    }
}

// ---------------------------------------------------------------------------
__global__ __launch_bounds__(NTHR, 1) void fused_kernel(
    const float* __restrict__ nullary,
    const float* __restrict__ unary,
    const float* __restrict__ binary,
    const float* __restrict__ andk,
    const float* __restrict__ ork,
    float* __restrict__ out)
{
    extern __shared__ char smx[];
    int bid = blockIdx.x;
    int tid = threadIdx.x;
    bool isProd = (tid >= 512);

    // GEMM unit list for this block (ascending; unary last if present)
    int ulist[4]; int n = 0;
    for (int u = bid; u < 520; u += NBLK) ulist[n++] = u;

    // ---- Phase 1: warp-specialized producer/consumer pipeline ----
    if (isProd) {
        stage_both_W(smx, andk);
        produce_unit(ulist[0], smx, 0, binary, unary);
    }
    __syncthreads();
    for (int i = 0; i < n; i++) {
        if (isProd) {
            if (i + 1 < n) produce_unit(ulist[i + 1], smx, (i + 1) & 1, binary, unary);
        } else {
            mma_and_store(smx, i & 1, ulist[i]);
        }
        __syncthreads();
    }

    // ---- Setup units (blocks 76: biases, 77: DN) ----
    if (bid == 76) {
        float* sred = (float*)smx;  // 24 x 8 partials (A0 area, now dead)
        if (tid < 192) {
            int row = tid >> 3, part = tid & 7;
            const float* w = andk + (size_t)row * NI + part * 80;
            float s = 0.f;
            #pragma unroll 8
            for (int k = 0; k < 80; k++) { float v = w[k]; s += v * v; }
            sred[row * 8 + part] = s;
        }
        __syncthreads();
        if (tid < NAC) {
            float s = 0.f;
            #pragma unroll
            for (int p = 0; p < 8; p++) s += sred[tid * 8 + p];
            g_andbias[tid] = THRv - s * TTHR;
        } else if (tid < 27) {
            int a = tid - NAC;
            float s = 0.f;
            #pragma unroll
            for (int c = 0; c < NC; c++) { float v = ork[a * NC + c]; s += v * v; }
            g_orbias[a] = s * TTHR - THRv;
        }
    } else if (bid == 77) {
        if (tid < NB * NAC) {
            int b = tid / NAC, ac = tid % NAC;
            const float* w = andk + (size_t)ac * NI;
            const float* nv = nullary + b * SEG;
            float s = 0.f;
            #pragma unroll 8
            for (int k = 0; k < SEG; k++) s += nv[k] * w[k];
            g_DN[tid] = s;
        }
    }

    // ---- Global barrier ----
    grid_barrier();

    // ---- Phase 2: combine (blocks 0..127, 8 gi each) ----
    if (bid < 128) {
        float* base   = (float*)smx;                   // 8 x 24
        float* red    = (float*)(smx + 1024);          // 8 x 64 x 17
        float* colmax = (float*)(smx + 1024 + 34816);  // 8 x 16
        int*   isLast = (int*)(smx + 1024 + 34816 + 512);

        int tile = tid >> 7;          // 0..7
        int t2   = tid & 127;
        int k    = t2 & 63;
        int half = t2 >> 6;
        int gi = bid * 8 + tile;
        int b = bid >> 3;             // uniform per block
        int i = gi & 63;

        if (tid < 192) {
            int tt = tid / NAC, c = tid % NAC;
            int i2 = (bid * 8 + tt) & 63;
            base[tt * NAC + c] = g_andbias[c] + g_DN[b * NAC + c]
                               + g_D[((size_t)(1024 + b) * 64 + i2) * 48 + c];
        }
        __syncthreads();

        bool act = (k < NK);
        int j  = k + (k >= i ? 1 : 0);
        int ip = (k < i) ? (i - 1) : i;
        const float4* du1 = (const float4*)(g_D + ((size_t)(1024 + b) * 64 + j) * 48 + 24 + half * 12);
        const float4* db0 = (const float4*)(g_D + ((size_t)gi * 64 + k) * 48 + half * 12);
        const float4* db1 = (const float4*)(g_D + ((size_t)(b * 64 + j) * 64 + ip) * 48 + 24 + half * 12);

        float s[12];
        if (act) {
            #pragma unroll
            for (int q = 0; q < 3; q++) {
                float4 u  = __ldg(du1 + q);
                float4 v0 = __ldg(db0 + q);
                float4 v1 = __ldg(db1 + q);
                int cb = half * 12 + 4 * q;
                s[4 * q + 0] = base[tile * NAC + cb + 0] + u.x + v0.x + v1.x;
                s[4 * q + 1] = base[tile * NAC + cb + 1] + u.y + v0.y + v1.y;
                s[4 * q + 2] = base[tile * NAC + cb + 2] + u.z + v0.z + v1.z;
                s[4 * q + 3] = base[tile * NAC + cb + 3] + u.w + v0.w + v1.w;
            }
        }

        float* redr = red + (tile * 64 + k) * 17;
        if (half == 0) {
            #pragma unroll
            for (int c = 0; c < 12; c++)
                redr[c] = act ? tanhapx(s[c]) : -2.0f;
        } else {
            #pragma unroll
            for (int c = 0; c < 4; c++)
                redr[12 + c] = act ? tanhapx(s[c]) : -2.0f;
            if (act) {
                float s2 = g_orbias[2];
                #pragma unroll
                for (int c = 0; c < NC; c++) s2 += tanhapx(s[4 + c]) * __ldg(ork + 16 + c);
                out[16 + NB * NO + (size_t)gi * NK + k] = s2;
            }
        }
        __syncthreads();

        if (t2 < 16) {
            float m = red[(tile * 64 + 0) * 17 + t2];
            #pragma unroll 8
            for (int r = 1; r < 64; r++) m = fmaxf(m, red[(tile * 64 + r) * 17 + t2]);
            colmax[tile * 16 + t2] = m;
        }
        __syncthreads();
        if (t2 == 0) {
            float s1 = g_orbias[1];
            #pragma unroll
            for (int c = 0; c < NC; c++) s1 += colmax[tile * 16 + 8 + c] * __ldg(ork + 8 + c);
            out[16 + gi] = s1;
        }
        if (t2 < NC) g_nullpart[gi * NC + t2] = colmax[tile * 16 + t2];

        // Fused final-null reduce: last of the 8 blocks for this b.
        __syncthreads();
        if (tid == 0) {
            __threadfence();
            int v = atomicAdd(&g_cnt[b], 1);
            *isLast = (v == 7) ? 1 : 0;
        }
        __syncthreads();
        if (*isLast) {
            __threadfence();
            if (tid < NC) {
                float m = -2.0f;
                #pragma unroll 8
                for (int r = 0; r < NO; r++)
                    m = fmaxf(m, g_nullpart[(b * NO + r) * NC + tid]);
                colmax[tid] = m;
            }
            __syncthreads();
            if (tid == 0) {
                float s0 = g_orbias[0];
                #pragma unroll
                for (int c = 0; c < NC; c++) s0 += colmax[c] * __ldg(ork + c);
                out[b] = s0;
                g_cnt[b] = 0;   // reset for next graph replay
            }
        }
    }
}

// ---------------------------------------------------------------------------
extern "C" void kernel_launch(void* const* d_in, const int* in_sizes, int n_in,
                              void* d_out, int out_size)
{
    const float* nullary = (const float*)d_in[0];
    const float* unary   = (const float*)d_in[1];
    const float* binary  = (const float*)d_in[2];
    const float* andk    = (const float*)d_in[3];
    const float* ork     = (const float*)d_in[4];
    float* out = (float*)d_out;

    cudaFuncSetAttribute(fused_kernel, cudaFuncAttributeMaxDynamicSharedMemorySize, S_TOTAL);
    fused_kernel<<<NBLK, NTHR, S_TOTAL>>>(nullary, unary, binary, andk, ork, out);
}